// round 8
// baseline (speedup 1.0000x reference)
#include <cuda_runtime.h>
#include <cuda_fp16.h>
#include <cstdint>

#define EMBED 768
#define HEAD 64
#define SEQ 4096
#define BATCH 4

// Projections, fp16. g_Qh/g_Kh: [B*T, 64] row-major. g_Vth: [B][64 head][4096 seq]
__device__ __half g_Qh[BATCH * SEQ * HEAD];
__device__ __half g_Kh[BATCH * SEQ * HEAD];
__device__ __half g_Vth[BATCH * HEAD * SEQ];
// Pre-transposed fp16 weights: g_WhT[m][n][e] = W_m[e][n]
__device__ __half g_WhT[3 * HEAD * EMBED];

__device__ __forceinline__ uint32_t h2_to_u32(__half2 h) {
    union { __half2 h; uint32_t u; } cvt;
    cvt.h = h;
    return cvt.u;
}
__device__ __forceinline__ __half2 u32_to_h2(uint32_t u) {
    union { uint32_t u; __half2 h; } cvt;
    cvt.u = u;
    return cvt.h;
}

// fp16: D(16x8,f32) += A(16x16,f16) * B(16x8,f16)
__device__ __forceinline__ void mma_f16(float c[4],
    uint32_t a0, uint32_t a1, uint32_t a2, uint32_t a3,
    uint32_t b0, uint32_t b1)
{
    asm volatile(
        "mma.sync.aligned.m16n8k16.row.col.f32.f16.f16.f32 "
        "{%0,%1,%2,%3}, {%4,%5,%6,%7}, {%8,%9}, {%0,%1,%2,%3};"
        : "+f"(c[0]), "+f"(c[1]), "+f"(c[2]), "+f"(c[3])
        : "r"(a0), "r"(a1), "r"(a2), "r"(a3), "r"(b0), "r"(b1));
}

__device__ __forceinline__ uint32_t s2u(const void* p) {
    uint32_t a;
    asm("{ .reg .u64 t; cvta.to.shared.u64 t, %1; cvt.u32.u64 %0, t; }"
        : "=r"(a) : "l"(p));
    return a;
}

#define CPA16(dst, src) \
    asm volatile("cp.async.cg.shared.global [%0], [%1], 16;" :: "r"(dst), "l"(src) : "memory")
#define CPA_COMMIT() asm volatile("cp.async.commit_group;" ::: "memory")
#define CPA_WAIT1()  asm volatile("cp.async.wait_group 1;" ::: "memory")
#define CPA_WAIT0()  asm volatile("cp.async.wait_group 0;" ::: "memory")

// ---------------------------------------------------------------------------
// Weight prep: g_WhT[m][n][e] = (half)W_m[e][n]
// ---------------------------------------------------------------------------
__global__ void wprep_kernel(const float* __restrict__ Wq,
                             const float* __restrict__ Wk,
                             const float* __restrict__ Wv)
{
    int idx = blockIdx.x * blockDim.x + threadIdx.x;
    if (idx >= 3 * HEAD * EMBED) return;
    int m = idx / (HEAD * EMBED);
    int r = idx - m * (HEAD * EMBED);
    int n = r / EMBED;
    int e = r - n * EMBED;
    const float* W = (m == 0) ? Wq : (m == 1) ? Wk : Wv;
    g_WhT[idx] = __float2half_rn(W[e * HEAD + n]);
}

// ---------------------------------------------------------------------------
// QKV projection via fp16 mma. BM=128, 256 threads, grid (128, 3).
// x converted fp32->fp16 during fill; W^T cp.async'd from g_WhT.
// smem: sxh half[128][72] (18432 B) + swh half[64][72] (9216 B)
// ---------------------------------------------------------------------------
__global__ __launch_bounds__(256, 2) void qkv_kernel(
    const float* __restrict__ x,
    const float* __restrict__ bq,
    const float* __restrict__ bk,
    const float* __restrict__ bv)
{
    extern __shared__ __align__(16) unsigned char qsm[];
    __half* sxh = (__half*)qsm;                 // 128 x 72
    __half* swh = (__half*)(qsm + 18432);       // 64 x 72

    const int m = blockIdx.y;
    const float* __restrict__ bias = (m == 0) ? bq : (m == 1) ? bk : bv;
    const __half* __restrict__ WT = g_WhT + (size_t)m * HEAD * EMBED;

    const int t    = threadIdx.x;
    const int lane = t & 31;
    const int w16  = (t >> 5) << 4;
    const int gid  = lane >> 2;
    const int l3   = lane & 3;
    const int l2   = 2 * l3;
    const int row0 = blockIdx.x * 128;

    const uint32_t swu = s2u(swh);

    float o[8][4];
#pragma unroll
    for (int n = 0; n < 8; n++)
#pragma unroll
        for (int c = 0; c < 4; c++) o[n][c] = 0.f;

    for (int e0 = 0; e0 < EMBED; e0 += 64) {
        __syncthreads();
        // W^T chunk via cp.async: 64 rows x 128 B
#pragma unroll
        for (int i = 0; i < 2; i++) {
            int id = t + i * 256;
            int n  = id >> 3;
            int ch = id & 7;
            CPA16(swu + n * 144 + 16 * ch, WT + (size_t)n * EMBED + e0 + 8 * ch);
        }
        CPA_COMMIT();
        // x chunk: 128 rows x 64 cols, fp32 -> fp16
#pragma unroll
        for (int i = 0; i < 8; i++) {
            int fi = t + i * 256;
            int r  = fi >> 4;
            int c  = (fi & 15) << 2;
            float4 xv = *(const float4*)&x[(size_t)(row0 + r) * EMBED + e0 + c];
            *(__half2*)&sxh[r * 72 + c]     = __floats2half2_rn(xv.x, xv.y);
            *(__half2*)&sxh[r * 72 + c + 2] = __floats2half2_rn(xv.z, xv.w);
        }
        CPA_WAIT0();
        __syncthreads();

#pragma unroll
        for (int ks = 0; ks < 4; ks++) {
            int k0 = 16 * ks;
            uint32_t a0 = *(const uint32_t*)&sxh[(w16 + gid) * 72 + k0 + l2];
            uint32_t a1 = *(const uint32_t*)&sxh[(w16 + gid + 8) * 72 + k0 + l2];
            uint32_t a2 = *(const uint32_t*)&sxh[(w16 + gid) * 72 + k0 + l2 + 8];
            uint32_t a3 = *(const uint32_t*)&sxh[(w16 + gid + 8) * 72 + k0 + l2 + 8];
#pragma unroll
            for (int n = 0; n < 8; n++) {
                uint32_t b0 = *(const uint32_t*)&swh[(8 * n + gid) * 72 + k0 + l2];
                uint32_t b1 = *(const uint32_t*)&swh[(8 * n + gid) * 72 + k0 + l2 + 8];
                mma_f16(o[n], a0, a1, a2, a3, b0, b1);
            }
        }
    }

    const int rowA = row0 + w16 + gid;
    const int rowB = rowA + 8;

    if (m < 2) {
        __half* outh = (m == 0) ? g_Qh : g_Kh;
#pragma unroll
        for (int n = 0; n < 8; n++) {
            int cb = 8 * n + l2;
            float b0 = bias[cb], b1 = bias[cb + 1];
            *(__half2*)&outh[(size_t)rowA * HEAD + cb] =
                __floats2half2_rn(o[n][0] + b0, o[n][1] + b1);
            *(__half2*)&outh[(size_t)rowB * HEAD + cb] =
                __floats2half2_rn(o[n][2] + b0, o[n][3] + b1);
        }
    } else {
        // V transposed: g_Vth[b][head][seq]
        const int bb   = row0 / SEQ;
        const int seqA = rowA - bb * SEQ;
        __half* vt = g_Vth + (size_t)bb * HEAD * SEQ;
#pragma unroll
        for (int n = 0; n < 8; n++) {
            int cb = 8 * n + l2;
            float b0 = bias[cb], b1 = bias[cb + 1];
            vt[(size_t)(cb)     * SEQ + seqA]     = __float2half_rn(o[n][0] + b0);
            vt[(size_t)(cb + 1) * SEQ + seqA]     = __float2half_rn(o[n][1] + b1);
            vt[(size_t)(cb)     * SEQ + seqA + 8] = __float2half_rn(o[n][2] + b0);
            vt[(size_t)(cb + 1) * SEQ + seqA + 8] = __float2half_rn(o[n][3] + b1);
        }
    }
}

// ---------------------------------------------------------------------------
// Flash attention, causal, fp16 m16n8k16, split-kn across 2 warp-groups.
// Q fragments register-resident (loop-invariant); P register-resident.
// Row-max reduced via one packed half2 shfl pair; l kept per-lane, reduced once.
// smem bytes: Q[0,9216) K[9216,27648) x2 stages, Vt[27648,46080) x2 stages.
// ---------------------------------------------------------------------------
__global__ __launch_bounds__(256, 2) void flash_kernel(float* __restrict__ out)
{
    extern __shared__ __align__(16) unsigned char smraw[];
    __half* sh = (__half*)smraw;
    __half* sQ = sh;                     // 64 x 72 halves

    const int b    = blockIdx.y;
    const int qt   = (int)gridDim.x - 1 - (int)blockIdx.x;  // heavy tiles first
    const int t    = threadIdx.x;
    const int lane = t & 31;
    const int warp = t >> 5;
    const int g    = warp >> 2;          // column-group 0/1
    const int w16  = (warp & 3) << 4;
    const int gid  = lane >> 2;
    const int l3   = lane & 3;
    const int r0   = w16 + gid;
    const int l2   = 2 * l3;

    const __half* __restrict__ Qg = g_Qh + (size_t)b * SEQ * HEAD;
    const __half* __restrict__ Kg = g_Kh + (size_t)b * SEQ * HEAD;
    const __half* __restrict__ Vg = g_Vth + (size_t)b * HEAD * SEQ;

    const uint32_t su = s2u(sh);

    // ---- prologue: Q + stage0(kt=0) ; stage1(kt=1) ----
#pragma unroll
    for (int i = 0; i < 2; i++) {
        int id = t + i * 256;
        int r  = id >> 3;
        int ch = id & 7;
        CPA16(su + r * 144 + 16 * ch, Qg + (size_t)(qt * 64 + r) * HEAD + 8 * ch);
        CPA16(su + 9216 + r * 144 + 16 * ch, Kg + (size_t)r * HEAD + 8 * ch);
        CPA16(su + 27648 + r * 144 + 16 * ch, Vg + (size_t)r * SEQ + 8 * ch);
    }
    CPA_COMMIT();
#pragma unroll
    for (int i = 0; i < 2; i++) {
        int id = t + i * 256;
        int r  = id >> 3;
        int ch = id & 7;
        CPA16(su + 9216 + 9216 + r * 144 + 16 * ch,
              Kg + (size_t)(64 + r) * HEAD + 8 * ch);
        CPA16(su + 27648 + 9216 + r * 144 + 16 * ch,
              Vg + (size_t)r * SEQ + 64 + 8 * ch);
    }
    CPA_COMMIT();

    // ---- preload Q fragments (loop-invariant across kt) ----
    CPA_WAIT1();            // group 0 (Q + stage0) landed
    __syncthreads();
    uint32_t qf[4][4];
#pragma unroll
    for (int ks = 0; ks < 4; ks++) {
        int k0 = 16 * ks;
        qf[ks][0] = *(const uint32_t*)&sQ[(r0) * 72 + k0 + l2];
        qf[ks][1] = *(const uint32_t*)&sQ[(r0 + 8) * 72 + k0 + l2];
        qf[ks][2] = *(const uint32_t*)&sQ[(r0) * 72 + k0 + l2 + 8];
        qf[ks][3] = *(const uint32_t*)&sQ[(r0 + 8) * 72 + k0 + l2 + 8];
    }

    float m0 = -1e30f, m1 = -1e30f, l0 = 0.f, l1 = 0.f;   // l per-lane partial
    float o[8][4];
#pragma unroll
    for (int n = 0; n < 8; n++)
#pragma unroll
        for (int c = 0; c < 4; c++) o[n][c] = 0.f;

    for (int kt = 0; kt <= qt; kt++) {
        CPA_WAIT1();
        __syncthreads();

        const int st = kt & 1;
        const __half* sKc = sh + 4608 + st * 4608;    // halves
        const __half* sVc = sh + 13824 + st * 4608;

        // S_half = Q(16x64) . K_half(32x64)^T ; 4 x k16 steps
        float s[4][4];
#pragma unroll
        for (int n = 0; n < 4; n++)
#pragma unroll
            for (int c = 0; c < 4; c++) s[n][c] = 0.f;

#pragma unroll
        for (int ks = 0; ks < 4; ks++) {
            int k0 = 16 * ks;
#pragma unroll
            for (int n = 0; n < 4; n++) {
                int kr = 32 * g + 8 * n + gid;
                uint32_t b0 = *(const uint32_t*)&sKc[kr * 72 + k0 + l2];
                uint32_t b1 = *(const uint32_t*)&sKc[kr * 72 + k0 + l2 + 8];
                mma_f16(s[n], qf[ks][0], qf[ks][1], qf[ks][2], qf[ks][3], b0, b1);
            }
        }

        // Scale + causal mask (diagonal tile only)
        const float scale = 0.125f;
        if (kt == qt) {
#pragma unroll
            for (int n = 0; n < 4; n++) {
                int c0 = 32 * g + 8 * n + l2;
                s[n][0] = (c0     <= r0    ) ? s[n][0] * scale : -1e30f;
                s[n][1] = (c0 + 1 <= r0    ) ? s[n][1] * scale : -1e30f;
                s[n][2] = (c0     <= r0 + 8) ? s[n][2] * scale : -1e30f;
                s[n][3] = (c0 + 1 <= r0 + 8) ? s[n][3] * scale : -1e30f;
            }
        } else {
#pragma unroll
            for (int n = 0; n < 4; n++)
#pragma unroll
                for (int c = 0; c < 4; c++) s[n][c] *= scale;
        }

        // Row max via packed half2 shfl (max is a shift; fp16 rounding harmless)
        float mx0 = fmaxf(fmaxf(s[0][0], s[0][1]), fmaxf(s[1][0], s[1][1]));
        mx0 = fmaxf(mx0, fmaxf(fmaxf(s[2][0], s[2][1]), fmaxf(s[3][0], s[3][1])));
        float mx1 = fmaxf(fmaxf(s[0][2], s[0][3]), fmaxf(s[1][2], s[1][3]));
        mx1 = fmaxf(mx1, fmaxf(fmaxf(s[2][2], s[2][3]), fmaxf(s[3][2], s[3][3])));

        __half2 hmx = __floats2half2_rn(mx0, mx1);
        hmx = __hmax2(hmx, u32_to_h2(__shfl_xor_sync(0xffffffffu, h2_to_u32(hmx), 1)));
        hmx = __hmax2(hmx, u32_to_h2(__shfl_xor_sync(0xffffffffu, h2_to_u32(hmx), 2)));
        float2 fmx = __half22float2(hmx);

        float mn0 = fmaxf(m0, fmx.x);
        float mn1 = fmaxf(m1, fmx.y);
        float alpha0 = __expf(m0 - mn0);
        float alpha1 = __expf(m1 - mn1);
        m0 = mn0; m1 = mn1;

        float rs0 = 0.f, rs1 = 0.f;
#pragma unroll
        for (int n = 0; n < 4; n++) {
            s[n][0] = __expf(s[n][0] - mn0);
            s[n][1] = __expf(s[n][1] - mn0);
            s[n][2] = __expf(s[n][2] - mn1);
            s[n][3] = __expf(s[n][3] - mn1);
            rs0 += s[n][0] + s[n][1];
            rs1 += s[n][2] + s[n][3];
        }
        l0 = l0 * alpha0 + rs0;          // per-lane partial; quad-reduced at end
        l1 = l1 * alpha1 + rs1;

#pragma unroll
        for (int n = 0; n < 8; n++) {
            o[n][0] *= alpha0; o[n][1] *= alpha0;
            o[n][2] *= alpha1; o[n][3] *= alpha1;
        }

        // Pack P into A-fragments directly (C-frag layout == A-frag layout)
        uint32_t p[8];
#pragma unroll
        for (int n = 0; n < 4; n++) {
            p[2 * n]     = h2_to_u32(__floats2half2_rn(s[n][0], s[n][1]));
            p[2 * n + 1] = h2_to_u32(__floats2half2_rn(s[n][2], s[n][3]));
        }

        // O += P_half(16x32) . V_half(32x64) ; 2 x k16 steps
#pragma unroll
        for (int ks = 0; ks < 2; ks++) {
            uint32_t a0 = p[4 * ks + 0];
            uint32_t a1 = p[4 * ks + 1];
            uint32_t a2 = p[4 * ks + 2];
            uint32_t a3 = p[4 * ks + 3];
            int kb = 32 * g + 16 * ks + l2;
#pragma unroll
            for (int n = 0; n < 8; n++) {
                int vr = 8 * n + gid;
                uint32_t b0 = *(const uint32_t*)&sVc[vr * 72 + kb];
                uint32_t b1 = *(const uint32_t*)&sVc[vr * 72 + kb + 8];
                mma_f16(o[n], a0, a1, a2, a3, b0, b1);
            }
        }

        __syncthreads();      // stage st fully consumed by all warps

        if (kt + 2 <= qt) {
#pragma unroll
            for (int i = 0; i < 2; i++) {
                int id = t + i * 256;
                int r  = id >> 3;
                int ch = id & 7;
                CPA16(su + 9216 + st * 9216 + r * 144 + 16 * ch,
                      Kg + (size_t)((kt + 2) * 64 + r) * HEAD + 8 * ch);
                CPA16(su + 27648 + st * 9216 + r * 144 + 16 * ch,
                      Vg + (size_t)r * SEQ + (kt + 2) * 64 + 8 * ch);
            }
        }
        CPA_COMMIT();
    }

    CPA_WAIT0();
    __syncthreads();

    // Quad-reduce the per-lane l partials (once, instead of per iteration)
    l0 += __shfl_xor_sync(0xffffffffu, l0, 1);
    l0 += __shfl_xor_sync(0xffffffffu, l0, 2);
    l1 += __shfl_xor_sync(0xffffffffu, l1, 1);
    l1 += __shfl_xor_sync(0xffffffffu, l1, 2);

    // ---- Merge the two groups' partial (m, l, O) ----
    float* sML = (float*)smraw;              // [2][64][2] floats (Q region)
    if (l3 == 0) {
        sML[((g * 64 + r0)     << 1) + 0] = m0;
        sML[((g * 64 + r0)     << 1) + 1] = l0;
        sML[((g * 64 + r0 + 8) << 1) + 0] = m1;
        sML[((g * 64 + r0 + 8) << 1) + 1] = l1;
    }
    __syncthreads();
    const int og = 1 - g;
    float mo0 = sML[((og * 64 + r0)     << 1) + 0];
    float lo0 = sML[((og * 64 + r0)     << 1) + 1];
    float mo1 = sML[((og * 64 + r0 + 8) << 1) + 0];
    float lo1 = sML[((og * 64 + r0 + 8) << 1) + 1];

    float M0 = fmaxf(m0, mo0), M1 = fmaxf(m1, mo1);
    float sc0 = __expf(m0 - M0), sc1 = __expf(m1 - M1);
    float L0 = l0 * sc0 + lo0 * __expf(mo0 - M0);
    float L1 = l1 * sc1 + lo1 * __expf(mo1 - M1);

#pragma unroll
    for (int n = 0; n < 8; n++) {
        o[n][0] *= sc0; o[n][1] *= sc0;
        o[n][2] *= sc1; o[n][3] *= sc1;
    }

    float* sOB = (float*)(smraw + 9216);     // 64 x 68 floats (K region)
    if (g == 1) {
#pragma unroll
        for (int n = 0; n < 8; n++) {
            int cb = 8 * n + l2;
            sOB[(r0) * 68 + cb + 0]     = o[n][0];
            sOB[(r0) * 68 + cb + 1]     = o[n][1];
            sOB[(r0 + 8) * 68 + cb + 0] = o[n][2];
            sOB[(r0 + 8) * 68 + cb + 1] = o[n][3];
        }
    }
    __syncthreads();
    if (g == 0) {
        float inv0 = 1.f / L0;
        float inv1 = 1.f / L1;
        size_t orow0 = (size_t)b * SEQ + qt * 64 + r0;
#pragma unroll
        for (int n = 0; n < 8; n++) {
            int cb = 8 * n + l2;
            float2 v0, v1;
            v0.x = (o[n][0] + sOB[(r0) * 68 + cb + 0])     * inv0;
            v0.y = (o[n][1] + sOB[(r0) * 68 + cb + 1])     * inv0;
            v1.x = (o[n][2] + sOB[(r0 + 8) * 68 + cb + 0]) * inv1;
            v1.y = (o[n][3] + sOB[(r0 + 8) * 68 + cb + 1]) * inv1;
            *(float2*)&out[orow0 * HEAD + cb]       = v0;
            *(float2*)&out[(orow0 + 8) * HEAD + cb] = v1;
        }
    }
}

extern "C" void kernel_launch(void* const* d_in, const int* in_sizes, int n_in,
                              void* d_out, int out_size)
{
    const float* x  = (const float*)d_in[0];
    const float* Wq = (const float*)d_in[1];
    const float* bq = (const float*)d_in[2];
    const float* Wk = (const float*)d_in[3];
    const float* bk = (const float*)d_in[4];
    const float* Wv = (const float*)d_in[5];
    const float* bv = (const float*)d_in[6];
    float* out = (float*)d_out;

    wprep_kernel<<<(3 * HEAD * EMBED + 255) / 256, 256>>>(Wq, Wk, Wv);

    const size_t QKV_SMEM = 27648;           // bytes: x 18432 + W 9216
    cudaFuncSetAttribute(qkv_kernel, cudaFuncAttributeMaxDynamicSharedMemorySize,
                         (int)QKV_SMEM);
    qkv_kernel<<<dim3(SEQ * BATCH / 128, 3), 256, QKV_SMEM>>>(x, bq, bk, bv);

    const size_t FLASH_SMEM = 46080;         // bytes: Q 9216 + K 2x9216 + Vt 2x9216
    cudaFuncSetAttribute(flash_kernel, cudaFuncAttributeMaxDynamicSharedMemorySize,
                         (int)FLASH_SMEM);
    flash_kernel<<<dim3(SEQ / 64, BATCH), 256, FLASH_SMEM>>>(out);
}

// round 9
// speedup vs baseline: 1.2995x; 1.2995x over previous
#include <cuda_runtime.h>
#include <cuda_fp16.h>
#include <cstdint>

#define EMBED 768
#define HEAD 64
#define SEQ 4096
#define BATCH 4

// Projections, fp16. g_Qh/g_Kh: [B*T, 64] row-major. g_Vth: [B][64 head][4096 seq]
__device__ __half g_Qh[BATCH * SEQ * HEAD];
__device__ __half g_Kh[BATCH * SEQ * HEAD];
__device__ __half g_Vth[BATCH * HEAD * SEQ];

__device__ __forceinline__ uint32_t f2tf32(float x) {
    uint32_t r;
    asm("cvt.rna.tf32.f32 %0, %1;" : "=r"(r) : "f"(x));
    return r;
}

__device__ __forceinline__ uint32_t h2_to_u32(__half2 h) {
    union { __half2 h; uint32_t u; } cvt;
    cvt.h = h;
    return cvt.u;
}
__device__ __forceinline__ __half2 u32_to_h2(uint32_t u) {
    union { uint32_t u; __half2 h; } cvt;
    cvt.u = u;
    return cvt.h;
}

// tf32: D(16x8) += A(16x8) * B(8x8)
__device__ __forceinline__ void mma_tf32(float c[4],
    uint32_t a0, uint32_t a1, uint32_t a2, uint32_t a3,
    uint32_t b0, uint32_t b1)
{
    asm volatile(
        "mma.sync.aligned.m16n8k8.row.col.f32.tf32.tf32.f32 "
        "{%0,%1,%2,%3}, {%4,%5,%6,%7}, {%8,%9}, {%0,%1,%2,%3};"
        : "+f"(c[0]), "+f"(c[1]), "+f"(c[2]), "+f"(c[3])
        : "r"(a0), "r"(a1), "r"(a2), "r"(a3), "r"(b0), "r"(b1));
}

// fp16: D(16x8,f32) += A(16x16,f16) * B(16x8,f16)
__device__ __forceinline__ void mma_f16(float c[4],
    uint32_t a0, uint32_t a1, uint32_t a2, uint32_t a3,
    uint32_t b0, uint32_t b1)
{
    asm volatile(
        "mma.sync.aligned.m16n8k16.row.col.f32.f16.f16.f32 "
        "{%0,%1,%2,%3}, {%4,%5,%6,%7}, {%8,%9}, {%0,%1,%2,%3};"
        : "+f"(c[0]), "+f"(c[1]), "+f"(c[2]), "+f"(c[3])
        : "r"(a0), "r"(a1), "r"(a2), "r"(a3), "r"(b0), "r"(b1));
}

__device__ __forceinline__ uint32_t s2u(const void* p) {
    uint32_t a;
    asm("{ .reg .u64 t; cvta.to.shared.u64 t, %1; cvt.u32.u64 %0, t; }"
        : "=r"(a) : "l"(p));
    return a;
}

#define CPA16(dst, src) \
    asm volatile("cp.async.cg.shared.global [%0], [%1], 16;" :: "r"(dst), "l"(src) : "memory")
#define CPA_COMMIT() asm volatile("cp.async.commit_group;" ::: "memory")
#define CPA_WAIT1()  asm volatile("cp.async.wait_group 1;" ::: "memory")
#define CPA_WAIT0()  asm volatile("cp.async.wait_group 0;" ::: "memory")

// ---------------------------------------------------------------------------
// QKV projection via tf32 mma (Round-7 known-good). BM=128, 256 threads,
// grid (128, 3). Q/K written as half2 [seq][head]; V transposed [head][seq].
// ---------------------------------------------------------------------------
__global__ __launch_bounds__(256, 2) void qkv_kernel(
    const float* __restrict__ x,
    const float* __restrict__ Wq, const float* __restrict__ bq,
    const float* __restrict__ Wk, const float* __restrict__ bk,
    const float* __restrict__ Wv, const float* __restrict__ bv)
{
    extern __shared__ uint32_t dsm[];
    uint32_t* sx = dsm;                 // 128 x 68
    uint32_t* sw = dsm + 128 * 68;      // 64 x 72

    const float* __restrict__ W;
    const float* __restrict__ bias;
    if (blockIdx.y == 0)      { W = Wq; bias = bq; }
    else if (blockIdx.y == 1) { W = Wk; bias = bk; }
    else                      { W = Wv; bias = bv; }

    const int t    = threadIdx.x;
    const int lane = t & 31;
    const int w16  = (t >> 5) << 4;
    const int gid  = lane >> 2;
    const int l3   = lane & 3;
    const int row0 = blockIdx.x * 128;

    float o[8][4];
#pragma unroll
    for (int n = 0; n < 8; n++)
#pragma unroll
        for (int c = 0; c < 4; c++) o[n][c] = 0.f;

    for (int e0 = 0; e0 < EMBED; e0 += 64) {
        __syncthreads();
#pragma unroll
        for (int i = 0; i < 8; i++) {
            int fi = t + i * 256;
            int r  = fi >> 4;
            int c  = (fi & 15) << 2;
            float4 xv = *(const float4*)&x[(size_t)(row0 + r) * EMBED + e0 + c];
            sx[r * 68 + c + 0] = f2tf32(xv.x);
            sx[r * 68 + c + 1] = f2tf32(xv.y);
            sx[r * 68 + c + 2] = f2tf32(xv.z);
            sx[r * 68 + c + 3] = f2tf32(xv.w);
        }
#pragma unroll
        for (int i = 0; i < 4; i++) {
            int fi = t + i * 256;
            int r  = fi >> 4;
            int c  = (fi & 15) << 2;
            float4 wv = *(const float4*)&W[(size_t)(e0 + r) * HEAD + c];
            sw[r * 72 + c + 0] = f2tf32(wv.x);
            sw[r * 72 + c + 1] = f2tf32(wv.y);
            sw[r * 72 + c + 2] = f2tf32(wv.z);
            sw[r * 72 + c + 3] = f2tf32(wv.w);
        }
        __syncthreads();

#pragma unroll
        for (int ks = 0; ks < 8; ks++) {
            int h = 8 * ks;
            uint32_t a0 = sx[(w16 + gid) * 68 + h + l3];
            uint32_t a1 = sx[(w16 + gid + 8) * 68 + h + l3];
            uint32_t a2 = sx[(w16 + gid) * 68 + h + l3 + 4];
            uint32_t a3 = sx[(w16 + gid + 8) * 68 + h + l3 + 4];
#pragma unroll
            for (int n = 0; n < 8; n++) {
                uint32_t b0 = sw[(h + l3) * 72 + 8 * n + gid];
                uint32_t b1 = sw[(h + l3 + 4) * 72 + 8 * n + gid];
                mma_tf32(o[n], a0, a1, a2, a3, b0, b1);
            }
        }
    }

    const int rowA = row0 + w16 + gid;
    const int rowB = rowA + 8;

    if (blockIdx.y < 2) {
        __half* outh = (blockIdx.y == 0) ? g_Qh : g_Kh;
#pragma unroll
        for (int n = 0; n < 8; n++) {
            int cb = 8 * n + 2 * l3;
            float b0 = bias[cb], b1 = bias[cb + 1];
            *(__half2*)&outh[(size_t)rowA * HEAD + cb] =
                __floats2half2_rn(o[n][0] + b0, o[n][1] + b1);
            *(__half2*)&outh[(size_t)rowB * HEAD + cb] =
                __floats2half2_rn(o[n][2] + b0, o[n][3] + b1);
        }
    } else {
        // V transposed: g_Vth[b][head][seq]
        const int bb   = row0 / SEQ;
        const int seqA = rowA - bb * SEQ;
        __half* vt = g_Vth + (size_t)bb * HEAD * SEQ;
#pragma unroll
        for (int n = 0; n < 8; n++) {
            int cb = 8 * n + 2 * l3;
            float b0 = bias[cb], b1 = bias[cb + 1];
            vt[(size_t)(cb)     * SEQ + seqA]     = __float2half_rn(o[n][0] + b0);
            vt[(size_t)(cb + 1) * SEQ + seqA]     = __float2half_rn(o[n][1] + b1);
            vt[(size_t)(cb)     * SEQ + seqA + 8] = __float2half_rn(o[n][2] + b0);
            vt[(size_t)(cb + 1) * SEQ + seqA + 8] = __float2half_rn(o[n][3] + b1);
        }
    }
}

// ---------------------------------------------------------------------------
// Flash attention, causal, fp16 m16n8k16, split-kn across 2 warp-groups.
// Q fragments register-resident (loop-invariant); P register-resident.
// Row-max via one packed half2 shfl pair; l per-lane, reduced once at the end.
// smem bytes: Q[0,9216) K[9216,27648) x2 stages, Vt[27648,46080) x2 stages.
// ---------------------------------------------------------------------------
__global__ __launch_bounds__(256, 2) void flash_kernel(float* __restrict__ out)
{
    extern __shared__ __align__(16) unsigned char smraw[];
    __half* sh = (__half*)smraw;
    __half* sQ = sh;                     // 64 x 72 halves

    const int b    = blockIdx.y;
    const int qt   = (int)gridDim.x - 1 - (int)blockIdx.x;  // heavy tiles first
    const int t    = threadIdx.x;
    const int lane = t & 31;
    const int warp = t >> 5;
    const int g    = warp >> 2;          // column-group 0/1
    const int w16  = (warp & 3) << 4;
    const int gid  = lane >> 2;
    const int l3   = lane & 3;
    const int r0   = w16 + gid;
    const int l2   = 2 * l3;

    const __half* __restrict__ Qg = g_Qh + (size_t)b * SEQ * HEAD;
    const __half* __restrict__ Kg = g_Kh + (size_t)b * SEQ * HEAD;
    const __half* __restrict__ Vg = g_Vth + (size_t)b * HEAD * SEQ;

    const uint32_t su = s2u(sh);

    // ---- prologue: Q + stage0(kt=0) ; stage1(kt=1) ----
#pragma unroll
    for (int i = 0; i < 2; i++) {
        int id = t + i * 256;
        int r  = id >> 3;
        int ch = id & 7;
        CPA16(su + r * 144 + 16 * ch, Qg + (size_t)(qt * 64 + r) * HEAD + 8 * ch);
        CPA16(su + 9216 + r * 144 + 16 * ch, Kg + (size_t)r * HEAD + 8 * ch);
        CPA16(su + 27648 + r * 144 + 16 * ch, Vg + (size_t)r * SEQ + 8 * ch);
    }
    CPA_COMMIT();
#pragma unroll
    for (int i = 0; i < 2; i++) {
        int id = t + i * 256;
        int r  = id >> 3;
        int ch = id & 7;
        CPA16(su + 9216 + 9216 + r * 144 + 16 * ch,
              Kg + (size_t)(64 + r) * HEAD + 8 * ch);
        CPA16(su + 27648 + 9216 + r * 144 + 16 * ch,
              Vg + (size_t)r * SEQ + 64 + 8 * ch);
    }
    CPA_COMMIT();

    // ---- preload Q fragments (loop-invariant across kt) ----
    CPA_WAIT1();            // group 0 (Q + stage0) landed
    __syncthreads();
    uint32_t qf[4][4];
#pragma unroll
    for (int ks = 0; ks < 4; ks++) {
        int k0 = 16 * ks;
        qf[ks][0] = *(const uint32_t*)&sQ[(r0) * 72 + k0 + l2];
        qf[ks][1] = *(const uint32_t*)&sQ[(r0 + 8) * 72 + k0 + l2];
        qf[ks][2] = *(const uint32_t*)&sQ[(r0) * 72 + k0 + l2 + 8];
        qf[ks][3] = *(const uint32_t*)&sQ[(r0 + 8) * 72 + k0 + l2 + 8];
    }

    float m0 = -1e30f, m1 = -1e30f, l0 = 0.f, l1 = 0.f;   // l = per-lane partial
    float o[8][4];
#pragma unroll
    for (int n = 0; n < 8; n++)
#pragma unroll
        for (int c = 0; c < 4; c++) o[n][c] = 0.f;

    for (int kt = 0; kt <= qt; kt++) {
        CPA_WAIT1();
        __syncthreads();

        const int st = kt & 1;
        const __half* sKc = sh + 4608 + st * 4608;    // halves
        const __half* sVc = sh + 13824 + st * 4608;

        // S_half = Q(16x64) . K_half(32x64)^T ; 4 x k16 steps
        float s[4][4];
#pragma unroll
        for (int n = 0; n < 4; n++)
#pragma unroll
            for (int c = 0; c < 4; c++) s[n][c] = 0.f;

#pragma unroll
        for (int ks = 0; ks < 4; ks++) {
            int k0 = 16 * ks;
#pragma unroll
            for (int n = 0; n < 4; n++) {
                int kr = 32 * g + 8 * n + gid;
                uint32_t b0 = *(const uint32_t*)&sKc[kr * 72 + k0 + l2];
                uint32_t b1 = *(const uint32_t*)&sKc[kr * 72 + k0 + l2 + 8];
                mma_f16(s[n], qf[ks][0], qf[ks][1], qf[ks][2], qf[ks][3], b0, b1);
            }
        }

        // Scale + causal mask (diagonal tile only)
        const float scale = 0.125f;
        if (kt == qt) {
#pragma unroll
            for (int n = 0; n < 4; n++) {
                int c0 = 32 * g + 8 * n + l2;
                s[n][0] = (c0     <= r0    ) ? s[n][0] * scale : -1e30f;
                s[n][1] = (c0 + 1 <= r0    ) ? s[n][1] * scale : -1e30f;
                s[n][2] = (c0     <= r0 + 8) ? s[n][2] * scale : -1e30f;
                s[n][3] = (c0 + 1 <= r0 + 8) ? s[n][3] * scale : -1e30f;
            }
        } else {
#pragma unroll
            for (int n = 0; n < 4; n++)
#pragma unroll
                for (int c = 0; c < 4; c++) s[n][c] *= scale;
        }

        // Row max via packed half2 shfl (max is a shift; fp16 rounding harmless)
        float mx0 = fmaxf(fmaxf(s[0][0], s[0][1]), fmaxf(s[1][0], s[1][1]));
        mx0 = fmaxf(mx0, fmaxf(fmaxf(s[2][0], s[2][1]), fmaxf(s[3][0], s[3][1])));
        float mx1 = fmaxf(fmaxf(s[0][2], s[0][3]), fmaxf(s[1][2], s[1][3]));
        mx1 = fmaxf(mx1, fmaxf(fmaxf(s[2][2], s[2][3]), fmaxf(s[3][2], s[3][3])));

        __half2 hmx = __floats2half2_rn(mx0, mx1);
        hmx = __hmax2(hmx, u32_to_h2(__shfl_xor_sync(0xffffffffu, h2_to_u32(hmx), 1)));
        hmx = __hmax2(hmx, u32_to_h2(__shfl_xor_sync(0xffffffffu, h2_to_u32(hmx), 2)));
        float2 fmx = __half22float2(hmx);

        float mn0 = fmaxf(m0, fmx.x);
        float mn1 = fmaxf(m1, fmx.y);
        float alpha0 = __expf(m0 - mn0);
        float alpha1 = __expf(m1 - mn1);
        m0 = mn0; m1 = mn1;

        float rs0 = 0.f, rs1 = 0.f;
#pragma unroll
        for (int n = 0; n < 4; n++) {
            s[n][0] = __expf(s[n][0] - mn0);
            s[n][1] = __expf(s[n][1] - mn0);
            s[n][2] = __expf(s[n][2] - mn1);
            s[n][3] = __expf(s[n][3] - mn1);
            rs0 += s[n][0] + s[n][1];
            rs1 += s[n][2] + s[n][3];
        }
        l0 = l0 * alpha0 + rs0;          // per-lane partial; quad-reduced at end
        l1 = l1 * alpha1 + rs1;

#pragma unroll
        for (int n = 0; n < 8; n++) {
            o[n][0] *= alpha0; o[n][1] *= alpha0;
            o[n][2] *= alpha1; o[n][3] *= alpha1;
        }

        // Pack P into A-fragments directly (C-frag layout == A-frag layout)
        uint32_t p[8];
#pragma unroll
        for (int n = 0; n < 4; n++) {
            p[2 * n]     = h2_to_u32(__floats2half2_rn(s[n][0], s[n][1]));
            p[2 * n + 1] = h2_to_u32(__floats2half2_rn(s[n][2], s[n][3]));
        }

        // O += P_half(16x32) . V_half(32x64) ; 2 x k16 steps
#pragma unroll
        for (int ks = 0; ks < 2; ks++) {
            uint32_t a0 = p[4 * ks + 0];
            uint32_t a1 = p[4 * ks + 1];
            uint32_t a2 = p[4 * ks + 2];
            uint32_t a3 = p[4 * ks + 3];
            int kb = 32 * g + 16 * ks + l2;
#pragma unroll
            for (int n = 0; n < 8; n++) {
                int vr = 8 * n + gid;
                uint32_t b0 = *(const uint32_t*)&sVc[vr * 72 + kb];
                uint32_t b1 = *(const uint32_t*)&sVc[vr * 72 + kb + 8];
                mma_f16(o[n], a0, a1, a2, a3, b0, b1);
            }
        }

        __syncthreads();      // stage st fully consumed by all warps

        if (kt + 2 <= qt) {
#pragma unroll
            for (int i = 0; i < 2; i++) {
                int id = t + i * 256;
                int r  = id >> 3;
                int ch = id & 7;
                CPA16(su + 9216 + st * 9216 + r * 144 + 16 * ch,
                      Kg + (size_t)((kt + 2) * 64 + r) * HEAD + 8 * ch);
                CPA16(su + 27648 + st * 9216 + r * 144 + 16 * ch,
                      Vg + (size_t)r * SEQ + (kt + 2) * 64 + 8 * ch);
            }
        }
        CPA_COMMIT();
    }

    CPA_WAIT0();
    __syncthreads();

    // Quad-reduce the per-lane l partials (once, instead of per iteration)
    l0 += __shfl_xor_sync(0xffffffffu, l0, 1);
    l0 += __shfl_xor_sync(0xffffffffu, l0, 2);
    l1 += __shfl_xor_sync(0xffffffffu, l1, 1);
    l1 += __shfl_xor_sync(0xffffffffu, l1, 2);

    // ---- Merge the two groups' partial (m, l, O) ----
    float* sML = (float*)smraw;              // [2][64][2] floats (Q region)
    if (l3 == 0) {
        sML[((g * 64 + r0)     << 1) + 0] = m0;
        sML[((g * 64 + r0)     << 1) + 1] = l0;
        sML[((g * 64 + r0 + 8) << 1) + 0] = m1;
        sML[((g * 64 + r0 + 8) << 1) + 1] = l1;
    }
    __syncthreads();
    const int og = 1 - g;
    float mo0 = sML[((og * 64 + r0)     << 1) + 0];
    float lo0 = sML[((og * 64 + r0)     << 1) + 1];
    float mo1 = sML[((og * 64 + r0 + 8) << 1) + 0];
    float lo1 = sML[((og * 64 + r0 + 8) << 1) + 1];

    float M0 = fmaxf(m0, mo0), M1 = fmaxf(m1, mo1);
    float sc0 = __expf(m0 - M0), sc1 = __expf(m1 - M1);
    float L0 = l0 * sc0 + lo0 * __expf(mo0 - M0);
    float L1 = l1 * sc1 + lo1 * __expf(mo1 - M1);

#pragma unroll
    for (int n = 0; n < 8; n++) {
        o[n][0] *= sc0; o[n][1] *= sc0;
        o[n][2] *= sc1; o[n][3] *= sc1;
    }

    float* sOB = (float*)(smraw + 9216);     // 64 x 68 floats (K region)
    if (g == 1) {
#pragma unroll
        for (int n = 0; n < 8; n++) {
            int cb = 8 * n + l2;
            sOB[(r0) * 68 + cb + 0]     = o[n][0];
            sOB[(r0) * 68 + cb + 1]     = o[n][1];
            sOB[(r0 + 8) * 68 + cb + 0] = o[n][2];
            sOB[(r0 + 8) * 68 + cb + 1] = o[n][3];
        }
    }
    __syncthreads();
    if (g == 0) {
        float inv0 = 1.f / L0;
        float inv1 = 1.f / L1;
        size_t orow0 = (size_t)b * SEQ + qt * 64 + r0;
#pragma unroll
        for (int n = 0; n < 8; n++) {
            int cb = 8 * n + l2;
            float2 v0, v1;
            v0.x = (o[n][0] + sOB[(r0) * 68 + cb + 0])     * inv0;
            v0.y = (o[n][1] + sOB[(r0) * 68 + cb + 1])     * inv0;
            v1.x = (o[n][2] + sOB[(r0 + 8) * 68 + cb + 0]) * inv1;
            v1.y = (o[n][3] + sOB[(r0 + 8) * 68 + cb + 1]) * inv1;
            *(float2*)&out[orow0 * HEAD + cb]       = v0;
            *(float2*)&out[(orow0 + 8) * HEAD + cb] = v1;
        }
    }
}

extern "C" void kernel_launch(void* const* d_in, const int* in_sizes, int n_in,
                              void* d_out, int out_size)
{
    const float* x  = (const float*)d_in[0];
    const float* Wq = (const float*)d_in[1];
    const float* bq = (const float*)d_in[2];
    const float* Wk = (const float*)d_in[3];
    const float* bk = (const float*)d_in[4];
    const float* Wv = (const float*)d_in[5];
    const float* bv = (const float*)d_in[6];
    float* out = (float*)d_out;

    const size_t QKV_SMEM = (size_t)(128 * 68 + 64 * 72) * sizeof(uint32_t);   // 53248
    cudaFuncSetAttribute(qkv_kernel, cudaFuncAttributeMaxDynamicSharedMemorySize,
                         (int)QKV_SMEM);
    qkv_kernel<<<dim3(SEQ * BATCH / 128, 3), 256, QKV_SMEM>>>(x, Wq, bq, Wk, bk, Wv, bv);

    const size_t FLASH_SMEM = 46080;         // bytes: Q 9216 + K 2x9216 + Vt 2x9216
    cudaFuncSetAttribute(flash_kernel, cudaFuncAttributeMaxDynamicSharedMemorySize,
                         (int)FLASH_SMEM);
    flash_kernel<<<dim3(SEQ / 64, BATCH), 256, FLASH_SMEM>>>(out);
}

// round 10
// speedup vs baseline: 1.3651x; 1.0504x over previous
#include <cuda_runtime.h>
#include <cuda_fp16.h>
#include <cstdint>

#define EMBED 768
#define HEAD 64
#define SEQ 4096
#define BATCH 4

// Projections, fp16. g_Qh/g_Kh: [B*T, 64] row-major. g_Vth: [B][64 head][4096 seq]
__device__ __half g_Qh[BATCH * SEQ * HEAD];
__device__ __half g_Kh[BATCH * SEQ * HEAD];
__device__ __half g_Vth[BATCH * HEAD * SEQ];

__device__ __forceinline__ uint32_t h2_to_u32(__half2 h) {
    union { __half2 h; uint32_t u; } cvt;
    cvt.h = h;
    return cvt.u;
}
__device__ __forceinline__ __half2 u32_to_h2(uint32_t u) {
    union { uint32_t u; __half2 h; } cvt;
    cvt.u = u;
    return cvt.h;
}

// tf32: D(16x8) += A(16x8) * B(8x8)  (raw fp32 bits are valid tf32 operands)
__device__ __forceinline__ void mma_tf32(float c[4],
    uint32_t a0, uint32_t a1, uint32_t a2, uint32_t a3,
    uint32_t b0, uint32_t b1)
{
    asm volatile(
        "mma.sync.aligned.m16n8k8.row.col.f32.tf32.tf32.f32 "
        "{%0,%1,%2,%3}, {%4,%5,%6,%7}, {%8,%9}, {%0,%1,%2,%3};"
        : "+f"(c[0]), "+f"(c[1]), "+f"(c[2]), "+f"(c[3])
        : "r"(a0), "r"(a1), "r"(a2), "r"(a3), "r"(b0), "r"(b1));
}

// fp16: D(16x8,f32) += A(16x16,f16) * B(16x8,f16)
__device__ __forceinline__ void mma_f16(float c[4],
    uint32_t a0, uint32_t a1, uint32_t a2, uint32_t a3,
    uint32_t b0, uint32_t b1)
{
    asm volatile(
        "mma.sync.aligned.m16n8k16.row.col.f32.f16.f16.f32 "
        "{%0,%1,%2,%3}, {%4,%5,%6,%7}, {%8,%9}, {%0,%1,%2,%3};"
        : "+f"(c[0]), "+f"(c[1]), "+f"(c[2]), "+f"(c[3])
        : "r"(a0), "r"(a1), "r"(a2), "r"(a3), "r"(b0), "r"(b1));
}

__device__ __forceinline__ uint32_t s2u(const void* p) {
    uint32_t a;
    asm("{ .reg .u64 t; cvta.to.shared.u64 t, %1; cvt.u32.u64 %0, t; }"
        : "=r"(a) : "l"(p));
    return a;
}

#define CPA16(dst, src) \
    asm volatile("cp.async.cg.shared.global [%0], [%1], 16;" :: "r"(dst), "l"(src) : "memory")
#define CPA_COMMIT() asm volatile("cp.async.commit_group;" ::: "memory")
#define CPA_WAIT1()  asm volatile("cp.async.wait_group 1;" ::: "memory")
#define CPA_WAIT0()  asm volatile("cp.async.wait_group 0;" ::: "memory")

// ---------------------------------------------------------------------------
// QKV projection, tf32 mma on raw-fp32 smem tiles, double-buffered cp.async.
// BM=128, 256 threads, grid (128, 3).
// smem (floats): x0[0,8704) x1[8704,17408) w0[17408,22016) w1[22016,26624)
//   x tiles 128x68 (row = 68 floats = 272 B, 16B-aligned)
//   w tiles 64x72  (row = 72 floats = 288 B, 16B-aligned)
// ---------------------------------------------------------------------------
__global__ __launch_bounds__(256, 2) void qkv_kernel(
    const float* __restrict__ x,
    const float* __restrict__ Wq, const float* __restrict__ bq,
    const float* __restrict__ Wk, const float* __restrict__ bk,
    const float* __restrict__ Wv, const float* __restrict__ bv)
{
    extern __shared__ __align__(16) float qsm[];
    const int X1 = 8704, W0 = 17408, W1 = 22016;

    const float* __restrict__ W;
    const float* __restrict__ bias;
    if (blockIdx.y == 0)      { W = Wq; bias = bq; }
    else if (blockIdx.y == 1) { W = Wk; bias = bk; }
    else                      { W = Wv; bias = bv; }

    const int t    = threadIdx.x;
    const int lane = t & 31;
    const int w16  = (t >> 5) << 4;
    const int gid  = lane >> 2;
    const int l3   = lane & 3;
    const int row0 = blockIdx.x * 128;

    const uint32_t su = s2u(qsm);

    // ---- prologue: chunk 0 then chunk 1 ----
#pragma unroll
    for (int st = 0; st < 2; st++) {
        int e0 = st * 64;
        uint32_t xbase = su + (st ? X1 : 0) * 4;
        uint32_t wbase = su + (st ? W1 : W0) * 4;
        // x: 128 rows x 64 floats = 2048 16B chunks; 8 per thread
#pragma unroll
        for (int i = 0; i < 8; i++) {
            int id = t + i * 256;
            int r  = id >> 4;
            int c  = (id & 15) << 2;
            CPA16(xbase + (r * 68 + c) * 4, &x[(size_t)(row0 + r) * EMBED + e0 + c]);
        }
        // W: 64 rows x 64 floats = 1024 chunks; 4 per thread
#pragma unroll
        for (int i = 0; i < 4; i++) {
            int id = t + i * 256;
            int r  = id >> 4;
            int c  = (id & 15) << 2;
            CPA16(wbase + (r * 72 + c) * 4, &W[(size_t)(e0 + r) * HEAD + c]);
        }
        CPA_COMMIT();
    }

    float o[8][4];
#pragma unroll
    for (int n = 0; n < 8; n++)
#pragma unroll
        for (int c = 0; c < 4; c++) o[n][c] = 0.f;

    for (int ch = 0; ch < EMBED / 64; ch++) {
        CPA_WAIT1();
        __syncthreads();

        const int st = ch & 1;
        const uint32_t* sx = (const uint32_t*)(qsm + (st ? X1 : 0));
        const uint32_t* sw = (const uint32_t*)(qsm + (st ? W1 : W0));

#pragma unroll
        for (int ks = 0; ks < 8; ks++) {
            int h = 8 * ks;
            uint32_t a0 = sx[(w16 + gid) * 68 + h + l3];
            uint32_t a1 = sx[(w16 + gid + 8) * 68 + h + l3];
            uint32_t a2 = sx[(w16 + gid) * 68 + h + l3 + 4];
            uint32_t a3 = sx[(w16 + gid + 8) * 68 + h + l3 + 4];
#pragma unroll
            for (int n = 0; n < 8; n++) {
                uint32_t b0 = sw[(h + l3) * 72 + 8 * n + gid];
                uint32_t b1 = sw[(h + l3 + 4) * 72 + 8 * n + gid];
                mma_tf32(o[n], a0, a1, a2, a3, b0, b1);
            }
        }

        __syncthreads();

        if (ch + 2 < EMBED / 64) {
            int e0 = (ch + 2) * 64;
            uint32_t xbase = su + (st ? X1 : 0) * 4;
            uint32_t wbase = su + (st ? W1 : W0) * 4;
#pragma unroll
            for (int i = 0; i < 8; i++) {
                int id = t + i * 256;
                int r  = id >> 4;
                int c  = (id & 15) << 2;
                CPA16(xbase + (r * 68 + c) * 4, &x[(size_t)(row0 + r) * EMBED + e0 + c]);
            }
#pragma unroll
            for (int i = 0; i < 4; i++) {
                int id = t + i * 256;
                int r  = id >> 4;
                int c  = (id & 15) << 2;
                CPA16(wbase + (r * 72 + c) * 4, &W[(size_t)(e0 + r) * HEAD + c]);
            }
        }
        CPA_COMMIT();
    }
    CPA_WAIT0();

    const int rowA = row0 + w16 + gid;
    const int rowB = rowA + 8;

    if (blockIdx.y < 2) {
        __half* outh = (blockIdx.y == 0) ? g_Qh : g_Kh;
#pragma unroll
        for (int n = 0; n < 8; n++) {
            int cb = 8 * n + 2 * l3;
            float b0 = bias[cb], b1 = bias[cb + 1];
            *(__half2*)&outh[(size_t)rowA * HEAD + cb] =
                __floats2half2_rn(o[n][0] + b0, o[n][1] + b1);
            *(__half2*)&outh[(size_t)rowB * HEAD + cb] =
                __floats2half2_rn(o[n][2] + b0, o[n][3] + b1);
        }
    } else {
        // V transposed: g_Vth[b][head][seq]
        const int bb   = row0 / SEQ;
        const int seqA = rowA - bb * SEQ;
        __half* vt = g_Vth + (size_t)bb * HEAD * SEQ;
#pragma unroll
        for (int n = 0; n < 8; n++) {
            int cb = 8 * n + 2 * l3;
            float b0 = bias[cb], b1 = bias[cb + 1];
            vt[(size_t)(cb)     * SEQ + seqA]     = __float2half_rn(o[n][0] + b0);
            vt[(size_t)(cb + 1) * SEQ + seqA]     = __float2half_rn(o[n][1] + b1);
            vt[(size_t)(cb)     * SEQ + seqA + 8] = __float2half_rn(o[n][2] + b0);
            vt[(size_t)(cb + 1) * SEQ + seqA + 8] = __float2half_rn(o[n][3] + b1);
        }
    }
}

// ---------------------------------------------------------------------------
// Flash attention (unchanged from Round 9): causal, fp16 m16n8k16, split-kn
// across 2 warp-groups, register-resident Q frags and P, cp.async K/V.
// smem bytes: Q[0,9216) K[9216,27648) x2 stages, Vt[27648,46080) x2 stages.
// ---------------------------------------------------------------------------
__global__ __launch_bounds__(256, 2) void flash_kernel(float* __restrict__ out)
{
    extern __shared__ __align__(16) unsigned char smraw[];
    __half* sh = (__half*)smraw;
    __half* sQ = sh;                     // 64 x 72 halves

    const int b    = blockIdx.y;
    const int qt   = (int)gridDim.x - 1 - (int)blockIdx.x;  // heavy tiles first
    const int t    = threadIdx.x;
    const int lane = t & 31;
    const int warp = t >> 5;
    const int g    = warp >> 2;          // column-group 0/1
    const int w16  = (warp & 3) << 4;
    const int gid  = lane >> 2;
    const int l3   = lane & 3;
    const int r0   = w16 + gid;
    const int l2   = 2 * l3;

    const __half* __restrict__ Qg = g_Qh + (size_t)b * SEQ * HEAD;
    const __half* __restrict__ Kg = g_Kh + (size_t)b * SEQ * HEAD;
    const __half* __restrict__ Vg = g_Vth + (size_t)b * HEAD * SEQ;

    const uint32_t su = s2u(sh);

#pragma unroll
    for (int i = 0; i < 2; i++) {
        int id = t + i * 256;
        int r  = id >> 3;
        int ch = id & 7;
        CPA16(su + r * 144 + 16 * ch, Qg + (size_t)(qt * 64 + r) * HEAD + 8 * ch);
        CPA16(su + 9216 + r * 144 + 16 * ch, Kg + (size_t)r * HEAD + 8 * ch);
        CPA16(su + 27648 + r * 144 + 16 * ch, Vg + (size_t)r * SEQ + 8 * ch);
    }
    CPA_COMMIT();
#pragma unroll
    for (int i = 0; i < 2; i++) {
        int id = t + i * 256;
        int r  = id >> 3;
        int ch = id & 7;
        CPA16(su + 9216 + 9216 + r * 144 + 16 * ch,
              Kg + (size_t)(64 + r) * HEAD + 8 * ch);
        CPA16(su + 27648 + 9216 + r * 144 + 16 * ch,
              Vg + (size_t)r * SEQ + 64 + 8 * ch);
    }
    CPA_COMMIT();

    CPA_WAIT1();
    __syncthreads();
    uint32_t qf[4][4];
#pragma unroll
    for (int ks = 0; ks < 4; ks++) {
        int k0 = 16 * ks;
        qf[ks][0] = *(const uint32_t*)&sQ[(r0) * 72 + k0 + l2];
        qf[ks][1] = *(const uint32_t*)&sQ[(r0 + 8) * 72 + k0 + l2];
        qf[ks][2] = *(const uint32_t*)&sQ[(r0) * 72 + k0 + l2 + 8];
        qf[ks][3] = *(const uint32_t*)&sQ[(r0 + 8) * 72 + k0 + l2 + 8];
    }

    float m0 = -1e30f, m1 = -1e30f, l0 = 0.f, l1 = 0.f;
    float o[8][4];
#pragma unroll
    for (int n = 0; n < 8; n++)
#pragma unroll
        for (int c = 0; c < 4; c++) o[n][c] = 0.f;

    for (int kt = 0; kt <= qt; kt++) {
        CPA_WAIT1();
        __syncthreads();

        const int st = kt & 1;
        const __half* sKc = sh + 4608 + st * 4608;
        const __half* sVc = sh + 13824 + st * 4608;

        float s[4][4];
#pragma unroll
        for (int n = 0; n < 4; n++)
#pragma unroll
            for (int c = 0; c < 4; c++) s[n][c] = 0.f;

#pragma unroll
        for (int ks = 0; ks < 4; ks++) {
            int k0 = 16 * ks;
#pragma unroll
            for (int n = 0; n < 4; n++) {
                int kr = 32 * g + 8 * n + gid;
                uint32_t b0 = *(const uint32_t*)&sKc[kr * 72 + k0 + l2];
                uint32_t b1 = *(const uint32_t*)&sKc[kr * 72 + k0 + l2 + 8];
                mma_f16(s[n], qf[ks][0], qf[ks][1], qf[ks][2], qf[ks][3], b0, b1);
            }
        }

        const float scale = 0.125f;
        if (kt == qt) {
#pragma unroll
            for (int n = 0; n < 4; n++) {
                int c0 = 32 * g + 8 * n + l2;
                s[n][0] = (c0     <= r0    ) ? s[n][0] * scale : -1e30f;
                s[n][1] = (c0 + 1 <= r0    ) ? s[n][1] * scale : -1e30f;
                s[n][2] = (c0     <= r0 + 8) ? s[n][2] * scale : -1e30f;
                s[n][3] = (c0 + 1 <= r0 + 8) ? s[n][3] * scale : -1e30f;
            }
        } else {
#pragma unroll
            for (int n = 0; n < 4; n++)
#pragma unroll
                for (int c = 0; c < 4; c++) s[n][c] *= scale;
        }

        float mx0 = fmaxf(fmaxf(s[0][0], s[0][1]), fmaxf(s[1][0], s[1][1]));
        mx0 = fmaxf(mx0, fmaxf(fmaxf(s[2][0], s[2][1]), fmaxf(s[3][0], s[3][1])));
        float mx1 = fmaxf(fmaxf(s[0][2], s[0][3]), fmaxf(s[1][2], s[1][3]));
        mx1 = fmaxf(mx1, fmaxf(fmaxf(s[2][2], s[2][3]), fmaxf(s[3][2], s[3][3])));

        __half2 hmx = __floats2half2_rn(mx0, mx1);
        hmx = __hmax2(hmx, u32_to_h2(__shfl_xor_sync(0xffffffffu, h2_to_u32(hmx), 1)));
        hmx = __hmax2(hmx, u32_to_h2(__shfl_xor_sync(0xffffffffu, h2_to_u32(hmx), 2)));
        float2 fmx = __half22float2(hmx);

        float mn0 = fmaxf(m0, fmx.x);
        float mn1 = fmaxf(m1, fmx.y);
        float alpha0 = __expf(m0 - mn0);
        float alpha1 = __expf(m1 - mn1);
        m0 = mn0; m1 = mn1;

        float rs0 = 0.f, rs1 = 0.f;
#pragma unroll
        for (int n = 0; n < 4; n++) {
            s[n][0] = __expf(s[n][0] - mn0);
            s[n][1] = __expf(s[n][1] - mn0);
            s[n][2] = __expf(s[n][2] - mn1);
            s[n][3] = __expf(s[n][3] - mn1);
            rs0 += s[n][0] + s[n][1];
            rs1 += s[n][2] + s[n][3];
        }
        l0 = l0 * alpha0 + rs0;
        l1 = l1 * alpha1 + rs1;

#pragma unroll
        for (int n = 0; n < 8; n++) {
            o[n][0] *= alpha0; o[n][1] *= alpha0;
            o[n][2] *= alpha1; o[n][3] *= alpha1;
        }

        uint32_t p[8];
#pragma unroll
        for (int n = 0; n < 4; n++) {
            p[2 * n]     = h2_to_u32(__floats2half2_rn(s[n][0], s[n][1]));
            p[2 * n + 1] = h2_to_u32(__floats2half2_rn(s[n][2], s[n][3]));
        }

#pragma unroll
        for (int ks = 0; ks < 2; ks++) {
            uint32_t a0 = p[4 * ks + 0];
            uint32_t a1 = p[4 * ks + 1];
            uint32_t a2 = p[4 * ks + 2];
            uint32_t a3 = p[4 * ks + 3];
            int kb = 32 * g + 16 * ks + l2;
#pragma unroll
            for (int n = 0; n < 8; n++) {
                int vr = 8 * n + gid;
                uint32_t b0 = *(const uint32_t*)&sVc[vr * 72 + kb];
                uint32_t b1 = *(const uint32_t*)&sVc[vr * 72 + kb + 8];
                mma_f16(o[n], a0, a1, a2, a3, b0, b1);
            }
        }

        __syncthreads();

        if (kt + 2 <= qt) {
#pragma unroll
            for (int i = 0; i < 2; i++) {
                int id = t + i * 256;
                int r  = id >> 3;
                int ch = id & 7;
                CPA16(su + 9216 + st * 9216 + r * 144 + 16 * ch,
                      Kg + (size_t)((kt + 2) * 64 + r) * HEAD + 8 * ch);
                CPA16(su + 27648 + st * 9216 + r * 144 + 16 * ch,
                      Vg + (size_t)r * SEQ + (kt + 2) * 64 + 8 * ch);
            }
        }
        CPA_COMMIT();
    }

    CPA_WAIT0();
    __syncthreads();

    l0 += __shfl_xor_sync(0xffffffffu, l0, 1);
    l0 += __shfl_xor_sync(0xffffffffu, l0, 2);
    l1 += __shfl_xor_sync(0xffffffffu, l1, 1);
    l1 += __shfl_xor_sync(0xffffffffu, l1, 2);

    float* sML = (float*)smraw;
    if (l3 == 0) {
        sML[((g * 64 + r0)     << 1) + 0] = m0;
        sML[((g * 64 + r0)     << 1) + 1] = l0;
        sML[((g * 64 + r0 + 8) << 1) + 0] = m1;
        sML[((g * 64 + r0 + 8) << 1) + 1] = l1;
    }
    __syncthreads();
    const int og = 1 - g;
    float mo0 = sML[((og * 64 + r0)     << 1) + 0];
    float lo0 = sML[((og * 64 + r0)     << 1) + 1];
    float mo1 = sML[((og * 64 + r0 + 8) << 1) + 0];
    float lo1 = sML[((og * 64 + r0 + 8) << 1) + 1];

    float M0 = fmaxf(m0, mo0), M1 = fmaxf(m1, mo1);
    float sc0 = __expf(m0 - M0), sc1 = __expf(m1 - M1);
    float L0 = l0 * sc0 + lo0 * __expf(mo0 - M0);
    float L1 = l1 * sc1 + lo1 * __expf(mo1 - M1);

#pragma unroll
    for (int n = 0; n < 8; n++) {
        o[n][0] *= sc0; o[n][1] *= sc0;
        o[n][2] *= sc1; o[n][3] *= sc1;
    }

    float* sOB = (float*)(smraw + 9216);
    if (g == 1) {
#pragma unroll
        for (int n = 0; n < 8; n++) {
            int cb = 8 * n + l2;
            sOB[(r0) * 68 + cb + 0]     = o[n][0];
            sOB[(r0) * 68 + cb + 1]     = o[n][1];
            sOB[(r0 + 8) * 68 + cb + 0] = o[n][2];
            sOB[(r0 + 8) * 68 + cb + 1] = o[n][3];
        }
    }
    __syncthreads();
    if (g == 0) {
        float inv0 = 1.f / L0;
        float inv1 = 1.f / L1;
        size_t orow0 = (size_t)b * SEQ + qt * 64 + r0;
#pragma unroll
        for (int n = 0; n < 8; n++) {
            int cb = 8 * n + l2;
            float2 v0, v1;
            v0.x = (o[n][0] + sOB[(r0) * 68 + cb + 0])     * inv0;
            v0.y = (o[n][1] + sOB[(r0) * 68 + cb + 1])     * inv0;
            v1.x = (o[n][2] + sOB[(r0 + 8) * 68 + cb + 0]) * inv1;
            v1.y = (o[n][3] + sOB[(r0 + 8) * 68 + cb + 1]) * inv1;
            *(float2*)&out[orow0 * HEAD + cb]       = v0;
            *(float2*)&out[(orow0 + 8) * HEAD + cb] = v1;
        }
    }
}

extern "C" void kernel_launch(void* const* d_in, const int* in_sizes, int n_in,
                              void* d_out, int out_size)
{
    const float* x  = (const float*)d_in[0];
    const float* Wq = (const float*)d_in[1];
    const float* bq = (const float*)d_in[2];
    const float* Wk = (const float*)d_in[3];
    const float* bk = (const float*)d_in[4];
    const float* Wv = (const float*)d_in[5];
    const float* bv = (const float*)d_in[6];
    float* out = (float*)d_out;

    const size_t QKV_SMEM = (size_t)26624 * sizeof(float);   // 106496 B
    cudaFuncSetAttribute(qkv_kernel, cudaFuncAttributeMaxDynamicSharedMemorySize,
                         (int)QKV_SMEM);
    qkv_kernel<<<dim3(SEQ * BATCH / 128, 3), 256, QKV_SMEM>>>(x, Wq, bq, Wk, bk, Wv, bv);

    const size_t FLASH_SMEM = 46080;         // bytes: Q 9216 + K 2x9216 + Vt 2x9216
    cudaFuncSetAttribute(flash_kernel, cudaFuncAttributeMaxDynamicSharedMemorySize,
                         (int)FLASH_SMEM);
    flash_kernel<<<dim3(SEQ / 64, BATCH), 256, FLASH_SMEM>>>(out);
}

// round 11
// speedup vs baseline: 1.5958x; 1.1690x over previous
#include <cuda_runtime.h>
#include <cuda_fp16.h>
#include <cstdint>

#define EMBED 768
#define HEAD 64
#define SEQ 4096
#define BATCH 4

// Projections, fp16. g_Qh/g_Kh: [B*T, 64] row-major. g_Vth: [B][64 head][4096 seq]
__device__ __half g_Qh[BATCH * SEQ * HEAD];
__device__ __half g_Kh[BATCH * SEQ * HEAD];
__device__ __half g_Vth[BATCH * HEAD * SEQ];
// tf32-rna pre-rounded weights, same [e][n] layout per matrix
__device__ float g_Wr[3 * EMBED * HEAD];

__device__ __forceinline__ uint32_t h2_to_u32(__half2 h) {
    union { __half2 h; uint32_t u; } cvt;
    cvt.h = h;
    return cvt.u;
}
__device__ __forceinline__ __half2 u32_to_h2(uint32_t u) {
    union { uint32_t u; __half2 h; } cvt;
    cvt.u = u;
    return cvt.h;
}

// tf32: D(16x8) += A(16x8) * B(8x8)
__device__ __forceinline__ void mma_tf32(float c[4],
    uint32_t a0, uint32_t a1, uint32_t a2, uint32_t a3,
    uint32_t b0, uint32_t b1)
{
    asm volatile(
        "mma.sync.aligned.m16n8k8.row.col.f32.tf32.tf32.f32 "
        "{%0,%1,%2,%3}, {%4,%5,%6,%7}, {%8,%9}, {%0,%1,%2,%3};"
        : "+f"(c[0]), "+f"(c[1]), "+f"(c[2]), "+f"(c[3])
        : "r"(a0), "r"(a1), "r"(a2), "r"(a3), "r"(b0), "r"(b1));
}

// fp16: D(16x8,f32) += A(16x16,f16) * B(16x8,f16)
__device__ __forceinline__ void mma_f16(float c[4],
    uint32_t a0, uint32_t a1, uint32_t a2, uint32_t a3,
    uint32_t b0, uint32_t b1)
{
    asm volatile(
        "mma.sync.aligned.m16n8k16.row.col.f32.f16.f16.f32 "
        "{%0,%1,%2,%3}, {%4,%5,%6,%7}, {%8,%9}, {%0,%1,%2,%3};"
        : "+f"(c[0]), "+f"(c[1]), "+f"(c[2]), "+f"(c[3])
        : "r"(a0), "r"(a1), "r"(a2), "r"(a3), "r"(b0), "r"(b1));
}

__device__ __forceinline__ uint32_t s2u(const void* p) {
    uint32_t a;
    asm("{ .reg .u64 t; cvta.to.shared.u64 t, %1; cvt.u32.u64 %0, t; }"
        : "=r"(a) : "l"(p));
    return a;
}

#define CPA16(dst, src) \
    asm volatile("cp.async.cg.shared.global [%0], [%1], 16;" :: "r"(dst), "l"(src) : "memory")
#define CPA_COMMIT() asm volatile("cp.async.commit_group;" ::: "memory")
#define CPA_WAIT1()  asm volatile("cp.async.wait_group 1;" ::: "memory")
#define CPA_WAIT0()  asm volatile("cp.async.wait_group 0;" ::: "memory")

// ---------------------------------------------------------------------------
// Weight prep: g_Wr = tf32-rna(W), fp32 bits (low 13 bits zero).
// ---------------------------------------------------------------------------
__global__ void wround_kernel(const float* __restrict__ Wq,
                              const float* __restrict__ Wk,
                              const float* __restrict__ Wv)
{
    int idx = blockIdx.x * blockDim.x + threadIdx.x;
    if (idx >= 3 * EMBED * HEAD) return;
    int m = idx / (EMBED * HEAD);
    int r = idx - m * (EMBED * HEAD);
    const float* W = (m == 0) ? Wq : (m == 1) ? Wk : Wv;
    uint32_t v;
    asm("cvt.rna.tf32.f32 %0, %1;" : "=r"(v) : "f"(W[r]));
    g_Wr[idx] = __uint_as_float(v);
}

// ---------------------------------------------------------------------------
// QKV projection, tf32 mma, double-buffered cp.async, BM=128, 256 threads,
// grid (128, 3). W pre-rounded (g_Wr); x rounded in-register (+0x1000 = rna).
// smem (floats): x0[0,8704) x1[8704,17408) w0[17408,22016) w1[22016,26624)
// ---------------------------------------------------------------------------
__global__ __launch_bounds__(256, 2) void qkv_kernel(
    const float* __restrict__ x,
    const float* __restrict__ bq,
    const float* __restrict__ bk,
    const float* __restrict__ bv)
{
    extern __shared__ __align__(16) float qsm[];
    const int X1 = 8704, W0 = 17408, W1 = 22016;

    const int m = blockIdx.y;
    const float* __restrict__ bias = (m == 0) ? bq : (m == 1) ? bk : bv;
    const float* __restrict__ W = g_Wr + (size_t)m * EMBED * HEAD;

    const int t    = threadIdx.x;
    const int lane = t & 31;
    const int w16  = (t >> 5) << 4;
    const int gid  = lane >> 2;
    const int l3   = lane & 3;
    const int row0 = blockIdx.x * 128;

    const uint32_t su = s2u(qsm);

    // ---- prologue: chunk 0 then chunk 1 ----
#pragma unroll
    for (int st = 0; st < 2; st++) {
        int e0 = st * 64;
        uint32_t xbase = su + (st ? X1 : 0) * 4;
        uint32_t wbase = su + (st ? W1 : W0) * 4;
#pragma unroll
        for (int i = 0; i < 8; i++) {
            int id = t + i * 256;
            int r  = id >> 4;
            int c  = (id & 15) << 2;
            CPA16(xbase + (r * 68 + c) * 4, &x[(size_t)(row0 + r) * EMBED + e0 + c]);
        }
#pragma unroll
        for (int i = 0; i < 4; i++) {
            int id = t + i * 256;
            int r  = id >> 4;
            int c  = (id & 15) << 2;
            CPA16(wbase + (r * 72 + c) * 4, &W[(size_t)(e0 + r) * HEAD + c]);
        }
        CPA_COMMIT();
    }

    float o[8][4];
#pragma unroll
    for (int n = 0; n < 8; n++)
#pragma unroll
        for (int c = 0; c < 4; c++) o[n][c] = 0.f;

    for (int ch = 0; ch < EMBED / 64; ch++) {
        CPA_WAIT1();
        __syncthreads();

        const int st = ch & 1;
        const uint32_t* sx = (const uint32_t*)(qsm + (st ? X1 : 0));
        const uint32_t* sw = (const uint32_t*)(qsm + (st ? W1 : W0));

#pragma unroll
        for (int ks = 0; ks < 8; ks++) {
            int h = 8 * ks;
            // +0x1000: add half tf32-ulp -> MMA's truncation becomes rna
            uint32_t a0 = sx[(w16 + gid) * 68 + h + l3] + 0x1000u;
            uint32_t a1 = sx[(w16 + gid + 8) * 68 + h + l3] + 0x1000u;
            uint32_t a2 = sx[(w16 + gid) * 68 + h + l3 + 4] + 0x1000u;
            uint32_t a3 = sx[(w16 + gid + 8) * 68 + h + l3 + 4] + 0x1000u;
#pragma unroll
            for (int n = 0; n < 8; n++) {
                uint32_t b0 = sw[(h + l3) * 72 + 8 * n + gid];
                uint32_t b1 = sw[(h + l3 + 4) * 72 + 8 * n + gid];
                mma_tf32(o[n], a0, a1, a2, a3, b0, b1);
            }
        }

        __syncthreads();

        if (ch + 2 < EMBED / 64) {
            int e0 = (ch + 2) * 64;
            uint32_t xbase = su + (st ? X1 : 0) * 4;
            uint32_t wbase = su + (st ? W1 : W0) * 4;
#pragma unroll
            for (int i = 0; i < 8; i++) {
                int id = t + i * 256;
                int r  = id >> 4;
                int c  = (id & 15) << 2;
                CPA16(xbase + (r * 68 + c) * 4, &x[(size_t)(row0 + r) * EMBED + e0 + c]);
            }
#pragma unroll
            for (int i = 0; i < 4; i++) {
                int id = t + i * 256;
                int r  = id >> 4;
                int c  = (id & 15) << 2;
                CPA16(wbase + (r * 72 + c) * 4, &W[(size_t)(e0 + r) * HEAD + c]);
            }
        }
        CPA_COMMIT();
    }
    CPA_WAIT0();

    const int rowA = row0 + w16 + gid;
    const int rowB = rowA + 8;

    if (m < 2) {
        __half* outh = (m == 0) ? g_Qh : g_Kh;
#pragma unroll
        for (int n = 0; n < 8; n++) {
            int cb = 8 * n + 2 * l3;
            float b0 = bias[cb], b1 = bias[cb + 1];
            *(__half2*)&outh[(size_t)rowA * HEAD + cb] =
                __floats2half2_rn(o[n][0] + b0, o[n][1] + b1);
            *(__half2*)&outh[(size_t)rowB * HEAD + cb] =
                __floats2half2_rn(o[n][2] + b0, o[n][3] + b1);
        }
    } else {
        // V transposed: g_Vth[b][head][seq]
        const int bb   = row0 / SEQ;
        const int seqA = rowA - bb * SEQ;
        __half* vt = g_Vth + (size_t)bb * HEAD * SEQ;
#pragma unroll
        for (int n = 0; n < 8; n++) {
            int cb = 8 * n + 2 * l3;
            float b0 = bias[cb], b1 = bias[cb + 1];
            vt[(size_t)(cb)     * SEQ + seqA]     = __float2half_rn(o[n][0] + b0);
            vt[(size_t)(cb + 1) * SEQ + seqA]     = __float2half_rn(o[n][1] + b1);
            vt[(size_t)(cb)     * SEQ + seqA + 8] = __float2half_rn(o[n][2] + b0);
            vt[(size_t)(cb + 1) * SEQ + seqA + 8] = __float2half_rn(o[n][3] + b1);
        }
    }
}

// ---------------------------------------------------------------------------
// Flash attention: causal, fp16 m16n8k16, split-kn across 2 warp-groups,
// register-resident Q frags + P, cp.async K/V double-buffer.
// LPT-balanced tile assignment: rank r (weight-desc) -> qt = 63 - r/4,
// batch = r & 3. bid<148 takes r=bid (heaviest, one per SM); bid>=148 takes
// r=403-bid so co-resident pairs (bid, bid+148) sum to ~constant load.
// smem bytes: Q[0,9216) K[9216,27648) x2 stages, Vt[27648,46080) x2 stages.
// ---------------------------------------------------------------------------
__global__ __launch_bounds__(256, 2) void flash_kernel(float* __restrict__ out)
{
    extern __shared__ __align__(16) unsigned char smraw[];
    __half* sh = (__half*)smraw;
    __half* sQ = sh;                     // 64 x 72 halves

    const int bid = blockIdx.x;
    const int rr  = (bid < 148) ? bid : 403 - bid;
    const int qt  = 63 - (rr >> 2);
    const int b   = rr & 3;

    const int t    = threadIdx.x;
    const int lane = t & 31;
    const int warp = t >> 5;
    const int g    = warp >> 2;          // column-group 0/1
    const int w16  = (warp & 3) << 4;
    const int gid  = lane >> 2;
    const int l3   = lane & 3;
    const int r0   = w16 + gid;
    const int l2   = 2 * l3;

    const __half* __restrict__ Qg = g_Qh + (size_t)b * SEQ * HEAD;
    const __half* __restrict__ Kg = g_Kh + (size_t)b * SEQ * HEAD;
    const __half* __restrict__ Vg = g_Vth + (size_t)b * HEAD * SEQ;

    const uint32_t su = s2u(sh);

#pragma unroll
    for (int i = 0; i < 2; i++) {
        int id = t + i * 256;
        int r  = id >> 3;
        int ch = id & 7;
        CPA16(su + r * 144 + 16 * ch, Qg + (size_t)(qt * 64 + r) * HEAD + 8 * ch);
        CPA16(su + 9216 + r * 144 + 16 * ch, Kg + (size_t)r * HEAD + 8 * ch);
        CPA16(su + 27648 + r * 144 + 16 * ch, Vg + (size_t)r * SEQ + 8 * ch);
    }
    CPA_COMMIT();
#pragma unroll
    for (int i = 0; i < 2; i++) {
        int id = t + i * 256;
        int r  = id >> 3;
        int ch = id & 7;
        CPA16(su + 9216 + 9216 + r * 144 + 16 * ch,
              Kg + (size_t)(64 + r) * HEAD + 8 * ch);
        CPA16(su + 27648 + 9216 + r * 144 + 16 * ch,
              Vg + (size_t)r * SEQ + 64 + 8 * ch);
    }
    CPA_COMMIT();

    CPA_WAIT1();
    __syncthreads();
    uint32_t qf[4][4];
#pragma unroll
    for (int ks = 0; ks < 4; ks++) {
        int k0 = 16 * ks;
        qf[ks][0] = *(const uint32_t*)&sQ[(r0) * 72 + k0 + l2];
        qf[ks][1] = *(const uint32_t*)&sQ[(r0 + 8) * 72 + k0 + l2];
        qf[ks][2] = *(const uint32_t*)&sQ[(r0) * 72 + k0 + l2 + 8];
        qf[ks][3] = *(const uint32_t*)&sQ[(r0 + 8) * 72 + k0 + l2 + 8];
    }

    float m0 = -1e30f, m1 = -1e30f, l0 = 0.f, l1 = 0.f;
    float o[8][4];
#pragma unroll
    for (int n = 0; n < 8; n++)
#pragma unroll
        for (int c = 0; c < 4; c++) o[n][c] = 0.f;

    for (int kt = 0; kt <= qt; kt++) {
        CPA_WAIT1();
        __syncthreads();

        const int st = kt & 1;
        const __half* sKc = sh + 4608 + st * 4608;
        const __half* sVc = sh + 13824 + st * 4608;

        float s[4][4];
#pragma unroll
        for (int n = 0; n < 4; n++)
#pragma unroll
            for (int c = 0; c < 4; c++) s[n][c] = 0.f;

#pragma unroll
        for (int ks = 0; ks < 4; ks++) {
            int k0 = 16 * ks;
#pragma unroll
            for (int n = 0; n < 4; n++) {
                int kr = 32 * g + 8 * n + gid;
                uint32_t b0 = *(const uint32_t*)&sKc[kr * 72 + k0 + l2];
                uint32_t b1 = *(const uint32_t*)&sKc[kr * 72 + k0 + l2 + 8];
                mma_f16(s[n], qf[ks][0], qf[ks][1], qf[ks][2], qf[ks][3], b0, b1);
            }
        }

        const float scale = 0.125f;
        if (kt == qt) {
#pragma unroll
            for (int n = 0; n < 4; n++) {
                int c0 = 32 * g + 8 * n + l2;
                s[n][0] = (c0     <= r0    ) ? s[n][0] * scale : -1e30f;
                s[n][1] = (c0 + 1 <= r0    ) ? s[n][1] * scale : -1e30f;
                s[n][2] = (c0     <= r0 + 8) ? s[n][2] * scale : -1e30f;
                s[n][3] = (c0 + 1 <= r0 + 8) ? s[n][3] * scale : -1e30f;
            }
        } else {
#pragma unroll
            for (int n = 0; n < 4; n++)
#pragma unroll
                for (int c = 0; c < 4; c++) s[n][c] *= scale;
        }

        float mx0 = fmaxf(fmaxf(s[0][0], s[0][1]), fmaxf(s[1][0], s[1][1]));
        mx0 = fmaxf(mx0, fmaxf(fmaxf(s[2][0], s[2][1]), fmaxf(s[3][0], s[3][1])));
        float mx1 = fmaxf(fmaxf(s[0][2], s[0][3]), fmaxf(s[1][2], s[1][3]));
        mx1 = fmaxf(mx1, fmaxf(fmaxf(s[2][2], s[2][3]), fmaxf(s[3][2], s[3][3])));

        __half2 hmx = __floats2half2_rn(mx0, mx1);
        hmx = __hmax2(hmx, u32_to_h2(__shfl_xor_sync(0xffffffffu, h2_to_u32(hmx), 1)));
        hmx = __hmax2(hmx, u32_to_h2(__shfl_xor_sync(0xffffffffu, h2_to_u32(hmx), 2)));
        float2 fmx = __half22float2(hmx);

        float mn0 = fmaxf(m0, fmx.x);
        float mn1 = fmaxf(m1, fmx.y);
        float alpha0 = __expf(m0 - mn0);
        float alpha1 = __expf(m1 - mn1);
        m0 = mn0; m1 = mn1;

        float rs0 = 0.f, rs1 = 0.f;
#pragma unroll
        for (int n = 0; n < 4; n++) {
            s[n][0] = __expf(s[n][0] - mn0);
            s[n][1] = __expf(s[n][1] - mn0);
            s[n][2] = __expf(s[n][2] - mn1);
            s[n][3] = __expf(s[n][3] - mn1);
            rs0 += s[n][0] + s[n][1];
            rs1 += s[n][2] + s[n][3];
        }
        l0 = l0 * alpha0 + rs0;
        l1 = l1 * alpha1 + rs1;

#pragma unroll
        for (int n = 0; n < 8; n++) {
            o[n][0] *= alpha0; o[n][1] *= alpha0;
            o[n][2] *= alpha1; o[n][3] *= alpha1;
        }

        uint32_t p[8];
#pragma unroll
        for (int n = 0; n < 4; n++) {
            p[2 * n]     = h2_to_u32(__floats2half2_rn(s[n][0], s[n][1]));
            p[2 * n + 1] = h2_to_u32(__floats2half2_rn(s[n][2], s[n][3]));
        }

#pragma unroll
        for (int ks = 0; ks < 2; ks++) {
            uint32_t a0 = p[4 * ks + 0];
            uint32_t a1 = p[4 * ks + 1];
            uint32_t a2 = p[4 * ks + 2];
            uint32_t a3 = p[4 * ks + 3];
            int kb = 32 * g + 16 * ks + l2;
#pragma unroll
            for (int n = 0; n < 8; n++) {
                int vr = 8 * n + gid;
                uint32_t b0 = *(const uint32_t*)&sVc[vr * 72 + kb];
                uint32_t b1 = *(const uint32_t*)&sVc[vr * 72 + kb + 8];
                mma_f16(o[n], a0, a1, a2, a3, b0, b1);
            }
        }

        __syncthreads();

        if (kt + 2 <= qt) {
#pragma unroll
            for (int i = 0; i < 2; i++) {
                int id = t + i * 256;
                int r  = id >> 3;
                int ch = id & 7;
                CPA16(su + 9216 + st * 9216 + r * 144 + 16 * ch,
                      Kg + (size_t)((kt + 2) * 64 + r) * HEAD + 8 * ch);
                CPA16(su + 27648 + st * 9216 + r * 144 + 16 * ch,
                      Vg + (size_t)r * SEQ + (kt + 2) * 64 + 8 * ch);
            }
        }
        CPA_COMMIT();
    }

    CPA_WAIT0();
    __syncthreads();

    l0 += __shfl_xor_sync(0xffffffffu, l0, 1);
    l0 += __shfl_xor_sync(0xffffffffu, l0, 2);
    l1 += __shfl_xor_sync(0xffffffffu, l1, 1);
    l1 += __shfl_xor_sync(0xffffffffu, l1, 2);

    float* sML = (float*)smraw;
    if (l3 == 0) {
        sML[((g * 64 + r0)     << 1) + 0] = m0;
        sML[((g * 64 + r0)     << 1) + 1] = l0;
        sML[((g * 64 + r0 + 8) << 1) + 0] = m1;
        sML[((g * 64 + r0 + 8) << 1) + 1] = l1;
    }
    __syncthreads();
    const int og = 1 - g;
    float mo0 = sML[((og * 64 + r0)     << 1) + 0];
    float lo0 = sML[((og * 64 + r0)     << 1) + 1];
    float mo1 = sML[((og * 64 + r0 + 8) << 1) + 0];
    float lo1 = sML[((og * 64 + r0 + 8) << 1) + 1];

    float M0 = fmaxf(m0, mo0), M1 = fmaxf(m1, mo1);
    float sc0 = __expf(m0 - M0), sc1 = __expf(m1 - M1);
    float L0 = l0 * sc0 + lo0 * __expf(mo0 - M0);
    float L1 = l1 * sc1 + lo1 * __expf(mo1 - M1);

#pragma unroll
    for (int n = 0; n < 8; n++) {
        o[n][0] *= sc0; o[n][1] *= sc0;
        o[n][2] *= sc1; o[n][3] *= sc1;
    }

    float* sOB = (float*)(smraw + 9216);
    if (g == 1) {
#pragma unroll
        for (int n = 0; n < 8; n++) {
            int cb = 8 * n + l2;
            sOB[(r0) * 68 + cb + 0]     = o[n][0];
            sOB[(r0) * 68 + cb + 1]     = o[n][1];
            sOB[(r0 + 8) * 68 + cb + 0] = o[n][2];
            sOB[(r0 + 8) * 68 + cb + 1] = o[n][3];
        }
    }
    __syncthreads();
    if (g == 0) {
        float inv0 = 1.f / L0;
        float inv1 = 1.f / L1;
        size_t orow0 = (size_t)b * SEQ + qt * 64 + r0;
#pragma unroll
        for (int n = 0; n < 8; n++) {
            int cb = 8 * n + l2;
            float2 v0, v1;
            v0.x = (o[n][0] + sOB[(r0) * 68 + cb + 0])     * inv0;
            v0.y = (o[n][1] + sOB[(r0) * 68 + cb + 1])     * inv0;
            v1.x = (o[n][2] + sOB[(r0 + 8) * 68 + cb + 0]) * inv1;
            v1.y = (o[n][3] + sOB[(r0 + 8) * 68 + cb + 1]) * inv1;
            *(float2*)&out[orow0 * HEAD + cb]       = v0;
            *(float2*)&out[(orow0 + 8) * HEAD + cb] = v1;
        }
    }
}

extern "C" void kernel_launch(void* const* d_in, const int* in_sizes, int n_in,
                              void* d_out, int out_size)
{
    const float* x  = (const float*)d_in[0];
    const float* Wq = (const float*)d_in[1];
    const float* bq = (const float*)d_in[2];
    const float* Wk = (const float*)d_in[3];
    const float* bk = (const float*)d_in[4];
    const float* Wv = (const float*)d_in[5];
    const float* bv = (const float*)d_in[6];
    float* out = (float*)d_out;

    wround_kernel<<<(3 * EMBED * HEAD + 255) / 256, 256>>>(Wq, Wk, Wv);

    const size_t QKV_SMEM = (size_t)26624 * sizeof(float);   // 106496 B
    cudaFuncSetAttribute(qkv_kernel, cudaFuncAttributeMaxDynamicSharedMemorySize,
                         (int)QKV_SMEM);
    qkv_kernel<<<dim3(SEQ * BATCH / 128, 3), 256, QKV_SMEM>>>(x, bq, bk, bv);

    const size_t FLASH_SMEM = 46080;         // bytes: Q 9216 + K 2x9216 + Vt 2x9216
    cudaFuncSetAttribute(flash_kernel, cudaFuncAttributeMaxDynamicSharedMemorySize,
                         (int)FLASH_SMEM);
    flash_kernel<<<SEQ / 64 * BATCH, 256, FLASH_SMEM>>>(out);
}

// round 12
// speedup vs baseline: 1.7193x; 1.0774x over previous
#include <cuda_runtime.h>
#include <cuda_fp16.h>
#include <cstdint>

#define EMBED 768
#define HEAD 64
#define SEQ 4096
#define BATCH 4

// Projections, fp16. g_Qh/g_Kh: [B*T, 64] row-major. g_Vth: [B][64 head][4096 seq]
__device__ __half g_Qh[BATCH * SEQ * HEAD];
__device__ __half g_Kh[BATCH * SEQ * HEAD];
__device__ __half g_Vth[BATCH * HEAD * SEQ];

__device__ __forceinline__ uint32_t h2_to_u32(__half2 h) {
    union { __half2 h; uint32_t u; } cvt;
    cvt.h = h;
    return cvt.u;
}
__device__ __forceinline__ __half2 u32_to_h2(uint32_t u) {
    union { uint32_t u; __half2 h; } cvt;
    cvt.u = u;
    return cvt.h;
}

// tf32: D(16x8) += A(16x8) * B(8x8)
__device__ __forceinline__ void mma_tf32(float c[4],
    uint32_t a0, uint32_t a1, uint32_t a2, uint32_t a3,
    uint32_t b0, uint32_t b1)
{
    asm volatile(
        "mma.sync.aligned.m16n8k8.row.col.f32.tf32.tf32.f32 "
        "{%0,%1,%2,%3}, {%4,%5,%6,%7}, {%8,%9}, {%0,%1,%2,%3};"
        : "+f"(c[0]), "+f"(c[1]), "+f"(c[2]), "+f"(c[3])
        : "r"(a0), "r"(a1), "r"(a2), "r"(a3), "r"(b0), "r"(b1));
}

// fp16: D(16x8,f32) += A(16x16,f16) * B(16x8,f16)
__device__ __forceinline__ void mma_f16(float c[4],
    uint32_t a0, uint32_t a1, uint32_t a2, uint32_t a3,
    uint32_t b0, uint32_t b1)
{
    asm volatile(
        "mma.sync.aligned.m16n8k16.row.col.f32.f16.f16.f32 "
        "{%0,%1,%2,%3}, {%4,%5,%6,%7}, {%8,%9}, {%0,%1,%2,%3};"
        : "+f"(c[0]), "+f"(c[1]), "+f"(c[2]), "+f"(c[3])
        : "r"(a0), "r"(a1), "r"(a2), "r"(a3), "r"(b0), "r"(b1));
}

__device__ __forceinline__ uint32_t s2u(const void* p) {
    uint32_t a;
    asm("{ .reg .u64 t; cvta.to.shared.u64 t, %1; cvt.u32.u64 %0, t; }"
        : "=r"(a) : "l"(p));
    return a;
}

#define CPA16(dst, src) \
    asm volatile("cp.async.cg.shared.global [%0], [%1], 16;" :: "r"(dst), "l"(src) : "memory")
#define CPA_COMMIT() asm volatile("cp.async.commit_group;" ::: "memory")
#define CPA_WAIT1()  asm volatile("cp.async.wait_group 1;" ::: "memory")
#define CPA_WAIT0()  asm volatile("cp.async.wait_group 0;" ::: "memory")

// ---------------------------------------------------------------------------
// Fused QKV projection: one block computes Q, K, V for 128 rows.
// tf32 mma on raw-fp32 smem tiles; rna rounding via in-register +0x1000 on
// BOTH operands (half-tf32-ulp then hardware truncation == cvt.rna).
// Grid = 128 blocks (single wave, 1 block/SM), 256 threads.
// smem (floats): x0[0,8704) x1[8704,17408)
//                W(stage s, matrix m) at 17408 + s*13824 + m*4608  (64x72)
// Total 45056 floats = 180224 B.
// ---------------------------------------------------------------------------
__global__ __launch_bounds__(256, 1) void qkv_fused_kernel(
    const float* __restrict__ x,
    const float* __restrict__ Wq, const float* __restrict__ bq,
    const float* __restrict__ Wk, const float* __restrict__ bk,
    const float* __restrict__ Wv, const float* __restrict__ bv)
{
    extern __shared__ __align__(16) float qsm[];
    const int XS = 8704, WBASE = 17408, WSTG = 13824, WMAT = 4608;

    const int t    = threadIdx.x;
    const int lane = t & 31;
    const int w16  = (t >> 5) << 4;
    const int gid  = lane >> 2;
    const int l3   = lane & 3;
    const int row0 = blockIdx.x * 128;

    const uint32_t su = s2u(qsm);

    // ---- prologue: chunks 0 and 1 ----
#pragma unroll
    for (int st = 0; st < 2; st++) {
        int e0 = st * 64;
        uint32_t xbase = su + (st * XS) * 4;
        uint32_t wbase = su + (WBASE + st * WSTG) * 4;
        // x: 128 rows x 64 floats = 2048 16B chunks; 8 per thread
#pragma unroll
        for (int i = 0; i < 8; i++) {
            int id = t + i * 256;
            int r  = id >> 4;
            int c  = (id & 15) << 2;
            CPA16(xbase + (r * 68 + c) * 4, &x[(size_t)(row0 + r) * EMBED + e0 + c]);
        }
        // W: 3 matrices x 64 rows x 16 chunks = 3072 chunks; 12 per thread
#pragma unroll
        for (int i = 0; i < 12; i++) {
            int id = t + i * 256;
            int m  = id >> 10;
            int rm = id & 1023;
            int r  = rm >> 4;
            int c  = (rm & 15) << 2;
            const float* Wm = (m == 0) ? Wq : (m == 1) ? Wk : Wv;
            CPA16(wbase + (m * WMAT + r * 72 + c) * 4, &Wm[(size_t)(e0 + r) * HEAD + c]);
        }
        CPA_COMMIT();
    }

    float o[3][8][4];
#pragma unroll
    for (int m = 0; m < 3; m++)
#pragma unroll
        for (int n = 0; n < 8; n++)
#pragma unroll
            for (int c = 0; c < 4; c++) o[m][n][c] = 0.f;

    for (int ch = 0; ch < EMBED / 64; ch++) {
        CPA_WAIT1();
        __syncthreads();

        const int st = ch & 1;
        const uint32_t* sx = (const uint32_t*)(qsm + st * XS);
        const uint32_t* sw = (const uint32_t*)(qsm + WBASE + st * WSTG);

#pragma unroll
        for (int ks = 0; ks < 8; ks++) {
            int h = 8 * ks;
            uint32_t a0 = sx[(w16 + gid) * 68 + h + l3] + 0x1000u;
            uint32_t a1 = sx[(w16 + gid + 8) * 68 + h + l3] + 0x1000u;
            uint32_t a2 = sx[(w16 + gid) * 68 + h + l3 + 4] + 0x1000u;
            uint32_t a3 = sx[(w16 + gid + 8) * 68 + h + l3 + 4] + 0x1000u;
#pragma unroll
            for (int m = 0; m < 3; m++) {
                const uint32_t* swm = sw + m * WMAT;
#pragma unroll
                for (int n = 0; n < 8; n++) {
                    uint32_t b0 = swm[(h + l3) * 72 + 8 * n + gid] + 0x1000u;
                    uint32_t b1 = swm[(h + l3 + 4) * 72 + 8 * n + gid] + 0x1000u;
                    mma_tf32(o[m][n], a0, a1, a2, a3, b0, b1);
                }
            }
        }

        __syncthreads();

        if (ch + 2 < EMBED / 64) {
            int e0 = (ch + 2) * 64;
            uint32_t xbase = su + (st * XS) * 4;
            uint32_t wbase = su + (WBASE + st * WSTG) * 4;
#pragma unroll
            for (int i = 0; i < 8; i++) {
                int id = t + i * 256;
                int r  = id >> 4;
                int c  = (id & 15) << 2;
                CPA16(xbase + (r * 68 + c) * 4, &x[(size_t)(row0 + r) * EMBED + e0 + c]);
            }
#pragma unroll
            for (int i = 0; i < 12; i++) {
                int id = t + i * 256;
                int m  = id >> 10;
                int rm = id & 1023;
                int r  = rm >> 4;
                int c  = (rm & 15) << 2;
                const float* Wm = (m == 0) ? Wq : (m == 1) ? Wk : Wv;
                CPA16(wbase + (m * WMAT + r * 72 + c) * 4, &Wm[(size_t)(e0 + r) * HEAD + c]);
            }
        }
        CPA_COMMIT();
    }
    CPA_WAIT0();

    const int rowA = row0 + w16 + gid;
    const int rowB = rowA + 8;

    // Q and K: [seq][head] fp16
#pragma unroll
    for (int m = 0; m < 2; m++) {
        const float* __restrict__ bias = (m == 0) ? bq : bk;
        __half* outh = (m == 0) ? g_Qh : g_Kh;
#pragma unroll
        for (int n = 0; n < 8; n++) {
            int cb = 8 * n + 2 * l3;
            float b0 = bias[cb], b1 = bias[cb + 1];
            *(__half2*)&outh[(size_t)rowA * HEAD + cb] =
                __floats2half2_rn(o[m][n][0] + b0, o[m][n][1] + b1);
            *(__half2*)&outh[(size_t)rowB * HEAD + cb] =
                __floats2half2_rn(o[m][n][2] + b0, o[m][n][3] + b1);
        }
    }
    // V transposed: g_Vth[b][head][seq]
    {
        const int bb   = row0 / SEQ;
        const int seqA = rowA - bb * SEQ;
        __half* vt = g_Vth + (size_t)bb * HEAD * SEQ;
#pragma unroll
        for (int n = 0; n < 8; n++) {
            int cb = 8 * n + 2 * l3;
            float b0 = bv[cb], b1 = bv[cb + 1];
            vt[(size_t)(cb)     * SEQ + seqA]     = __float2half_rn(o[2][n][0] + b0);
            vt[(size_t)(cb + 1) * SEQ + seqA]     = __float2half_rn(o[2][n][1] + b1);
            vt[(size_t)(cb)     * SEQ + seqA + 8] = __float2half_rn(o[2][n][2] + b0);
            vt[(size_t)(cb + 1) * SEQ + seqA + 8] = __float2half_rn(o[2][n][3] + b1);
        }
    }
}

// ---------------------------------------------------------------------------
// Flash attention (unchanged from Round 11): causal, fp16 m16n8k16, split-kn
// across 2 warp-groups, register-resident Q frags + P, cp.async double-buffer,
// LPT-balanced tile assignment.
// smem bytes: Q[0,9216) K[9216,27648) x2 stages, Vt[27648,46080) x2 stages.
// ---------------------------------------------------------------------------
__global__ __launch_bounds__(256, 2) void flash_kernel(float* __restrict__ out)
{
    extern __shared__ __align__(16) unsigned char smraw[];
    __half* sh = (__half*)smraw;
    __half* sQ = sh;                     // 64 x 72 halves

    const int bid = blockIdx.x;
    const int rr  = (bid < 148) ? bid : 403 - bid;
    const int qt  = 63 - (rr >> 2);
    const int b   = rr & 3;

    const int t    = threadIdx.x;
    const int lane = t & 31;
    const int warp = t >> 5;
    const int g    = warp >> 2;          // column-group 0/1
    const int w16  = (warp & 3) << 4;
    const int gid  = lane >> 2;
    const int l3   = lane & 3;
    const int r0   = w16 + gid;
    const int l2   = 2 * l3;

    const __half* __restrict__ Qg = g_Qh + (size_t)b * SEQ * HEAD;
    const __half* __restrict__ Kg = g_Kh + (size_t)b * SEQ * HEAD;
    const __half* __restrict__ Vg = g_Vth + (size_t)b * HEAD * SEQ;

    const uint32_t su = s2u(sh);

#pragma unroll
    for (int i = 0; i < 2; i++) {
        int id = t + i * 256;
        int r  = id >> 3;
        int ch = id & 7;
        CPA16(su + r * 144 + 16 * ch, Qg + (size_t)(qt * 64 + r) * HEAD + 8 * ch);
        CPA16(su + 9216 + r * 144 + 16 * ch, Kg + (size_t)r * HEAD + 8 * ch);
        CPA16(su + 27648 + r * 144 + 16 * ch, Vg + (size_t)r * SEQ + 8 * ch);
    }
    CPA_COMMIT();
#pragma unroll
    for (int i = 0; i < 2; i++) {
        int id = t + i * 256;
        int r  = id >> 3;
        int ch = id & 7;
        CPA16(su + 9216 + 9216 + r * 144 + 16 * ch,
              Kg + (size_t)(64 + r) * HEAD + 8 * ch);
        CPA16(su + 27648 + 9216 + r * 144 + 16 * ch,
              Vg + (size_t)r * SEQ + 64 + 8 * ch);
    }
    CPA_COMMIT();

    CPA_WAIT1();
    __syncthreads();
    uint32_t qf[4][4];
#pragma unroll
    for (int ks = 0; ks < 4; ks++) {
        int k0 = 16 * ks;
        qf[ks][0] = *(const uint32_t*)&sQ[(r0) * 72 + k0 + l2];
        qf[ks][1] = *(const uint32_t*)&sQ[(r0 + 8) * 72 + k0 + l2];
        qf[ks][2] = *(const uint32_t*)&sQ[(r0) * 72 + k0 + l2 + 8];
        qf[ks][3] = *(const uint32_t*)&sQ[(r0 + 8) * 72 + k0 + l2 + 8];
    }

    float m0 = -1e30f, m1 = -1e30f, l0 = 0.f, l1 = 0.f;
    float o[8][4];
#pragma unroll
    for (int n = 0; n < 8; n++)
#pragma unroll
        for (int c = 0; c < 4; c++) o[n][c] = 0.f;

    for (int kt = 0; kt <= qt; kt++) {
        CPA_WAIT1();
        __syncthreads();

        const int st = kt & 1;
        const __half* sKc = sh + 4608 + st * 4608;
        const __half* sVc = sh + 13824 + st * 4608;

        float s[4][4];
#pragma unroll
        for (int n = 0; n < 4; n++)
#pragma unroll
            for (int c = 0; c < 4; c++) s[n][c] = 0.f;

#pragma unroll
        for (int ks = 0; ks < 4; ks++) {
            int k0 = 16 * ks;
#pragma unroll
            for (int n = 0; n < 4; n++) {
                int kr = 32 * g + 8 * n + gid;
                uint32_t b0 = *(const uint32_t*)&sKc[kr * 72 + k0 + l2];
                uint32_t b1 = *(const uint32_t*)&sKc[kr * 72 + k0 + l2 + 8];
                mma_f16(s[n], qf[ks][0], qf[ks][1], qf[ks][2], qf[ks][3], b0, b1);
            }
        }

        const float scale = 0.125f;
        if (kt == qt) {
#pragma unroll
            for (int n = 0; n < 4; n++) {
                int c0 = 32 * g + 8 * n + l2;
                s[n][0] = (c0     <= r0    ) ? s[n][0] * scale : -1e30f;
                s[n][1] = (c0 + 1 <= r0    ) ? s[n][1] * scale : -1e30f;
                s[n][2] = (c0     <= r0 + 8) ? s[n][2] * scale : -1e30f;
                s[n][3] = (c0 + 1 <= r0 + 8) ? s[n][3] * scale : -1e30f;
            }
        } else {
#pragma unroll
            for (int n = 0; n < 4; n++)
#pragma unroll
                for (int c = 0; c < 4; c++) s[n][c] *= scale;
        }

        float mx0 = fmaxf(fmaxf(s[0][0], s[0][1]), fmaxf(s[1][0], s[1][1]));
        mx0 = fmaxf(mx0, fmaxf(fmaxf(s[2][0], s[2][1]), fmaxf(s[3][0], s[3][1])));
        float mx1 = fmaxf(fmaxf(s[0][2], s[0][3]), fmaxf(s[1][2], s[1][3]));
        mx1 = fmaxf(mx1, fmaxf(fmaxf(s[2][2], s[2][3]), fmaxf(s[3][2], s[3][3])));

        __half2 hmx = __floats2half2_rn(mx0, mx1);
        hmx = __hmax2(hmx, u32_to_h2(__shfl_xor_sync(0xffffffffu, h2_to_u32(hmx), 1)));
        hmx = __hmax2(hmx, u32_to_h2(__shfl_xor_sync(0xffffffffu, h2_to_u32(hmx), 2)));
        float2 fmx = __half22float2(hmx);

        float mn0 = fmaxf(m0, fmx.x);
        float mn1 = fmaxf(m1, fmx.y);
        float alpha0 = __expf(m0 - mn0);
        float alpha1 = __expf(m1 - mn1);
        m0 = mn0; m1 = mn1;

        float rs0 = 0.f, rs1 = 0.f;
#pragma unroll
        for (int n = 0; n < 4; n++) {
            s[n][0] = __expf(s[n][0] - mn0);
            s[n][1] = __expf(s[n][1] - mn0);
            s[n][2] = __expf(s[n][2] - mn1);
            s[n][3] = __expf(s[n][3] - mn1);
            rs0 += s[n][0] + s[n][1];
            rs1 += s[n][2] + s[n][3];
        }
        l0 = l0 * alpha0 + rs0;
        l1 = l1 * alpha1 + rs1;

#pragma unroll
        for (int n = 0; n < 8; n++) {
            o[n][0] *= alpha0; o[n][1] *= alpha0;
            o[n][2] *= alpha1; o[n][3] *= alpha1;
        }

        uint32_t p[8];
#pragma unroll
        for (int n = 0; n < 4; n++) {
            p[2 * n]     = h2_to_u32(__floats2half2_rn(s[n][0], s[n][1]));
            p[2 * n + 1] = h2_to_u32(__floats2half2_rn(s[n][2], s[n][3]));
        }

#pragma unroll
        for (int ks = 0; ks < 2; ks++) {
            uint32_t a0 = p[4 * ks + 0];
            uint32_t a1 = p[4 * ks + 1];
            uint32_t a2 = p[4 * ks + 2];
            uint32_t a3 = p[4 * ks + 3];
            int kb = 32 * g + 16 * ks + l2;
#pragma unroll
            for (int n = 0; n < 8; n++) {
                int vr = 8 * n + gid;
                uint32_t b0 = *(const uint32_t*)&sVc[vr * 72 + kb];
                uint32_t b1 = *(const uint32_t*)&sVc[vr * 72 + kb + 8];
                mma_f16(o[n], a0, a1, a2, a3, b0, b1);
            }
        }

        __syncthreads();

        if (kt + 2 <= qt) {
#pragma unroll
            for (int i = 0; i < 2; i++) {
                int id = t + i * 256;
                int r  = id >> 3;
                int ch = id & 7;
                CPA16(su + 9216 + st * 9216 + r * 144 + 16 * ch,
                      Kg + (size_t)((kt + 2) * 64 + r) * HEAD + 8 * ch);
                CPA16(su + 27648 + st * 9216 + r * 144 + 16 * ch,
                      Vg + (size_t)r * SEQ + (kt + 2) * 64 + 8 * ch);
            }
        }
        CPA_COMMIT();
    }

    CPA_WAIT0();
    __syncthreads();

    l0 += __shfl_xor_sync(0xffffffffu, l0, 1);
    l0 += __shfl_xor_sync(0xffffffffu, l0, 2);
    l1 += __shfl_xor_sync(0xffffffffu, l1, 1);
    l1 += __shfl_xor_sync(0xffffffffu, l1, 2);

    float* sML = (float*)smraw;
    if (l3 == 0) {
        sML[((g * 64 + r0)     << 1) + 0] = m0;
        sML[((g * 64 + r0)     << 1) + 1] = l0;
        sML[((g * 64 + r0 + 8) << 1) + 0] = m1;
        sML[((g * 64 + r0 + 8) << 1) + 1] = l1;
    }
    __syncthreads();
    const int og = 1 - g;
    float mo0 = sML[((og * 64 + r0)     << 1) + 0];
    float lo0 = sML[((og * 64 + r0)     << 1) + 1];
    float mo1 = sML[((og * 64 + r0 + 8) << 1) + 0];
    float lo1 = sML[((og * 64 + r0 + 8) << 1) + 1];

    float M0 = fmaxf(m0, mo0), M1 = fmaxf(m1, mo1);
    float sc0 = __expf(m0 - M0), sc1 = __expf(m1 - M1);
    float L0 = l0 * sc0 + lo0 * __expf(mo0 - M0);
    float L1 = l1 * sc1 + lo1 * __expf(mo1 - M1);

#pragma unroll
    for (int n = 0; n < 8; n++) {
        o[n][0] *= sc0; o[n][1] *= sc0;
        o[n][2] *= sc1; o[n][3] *= sc1;
    }

    float* sOB = (float*)(smraw + 9216);
    if (g == 1) {
#pragma unroll
        for (int n = 0; n < 8; n++) {
            int cb = 8 * n + l2;
            sOB[(r0) * 68 + cb + 0]     = o[n][0];
            sOB[(r0) * 68 + cb + 1]     = o[n][1];
            sOB[(r0 + 8) * 68 + cb + 0] = o[n][2];
            sOB[(r0 + 8) * 68 + cb + 1] = o[n][3];
        }
    }
    __syncthreads();
    if (g == 0) {
        float inv0 = 1.f / L0;
        float inv1 = 1.f / L1;
        size_t orow0 = (size_t)b * SEQ + qt * 64 + r0;
#pragma unroll
        for (int n = 0; n < 8; n++) {
            int cb = 8 * n + l2;
            float2 v0, v1;
            v0.x = (o[n][0] + sOB[(r0) * 68 + cb + 0])     * inv0;
            v0.y = (o[n][1] + sOB[(r0) * 68 + cb + 1])     * inv0;
            v1.x = (o[n][2] + sOB[(r0 + 8) * 68 + cb + 0]) * inv1;
            v1.y = (o[n][3] + sOB[(r0 + 8) * 68 + cb + 1]) * inv1;
            *(float2*)&out[orow0 * HEAD + cb]       = v0;
            *(float2*)&out[(orow0 + 8) * HEAD + cb] = v1;
        }
    }
}

extern "C" void kernel_launch(void* const* d_in, const int* in_sizes, int n_in,
                              void* d_out, int out_size)
{
    const float* x  = (const float*)d_in[0];
    const float* Wq = (const float*)d_in[1];
    const float* bq = (const float*)d_in[2];
    const float* Wk = (const float*)d_in[3];
    const float* bk = (const float*)d_in[4];
    const float* Wv = (const float*)d_in[5];
    const float* bv = (const float*)d_in[6];
    float* out = (float*)d_out;

    const size_t QKV_SMEM = (size_t)45056 * sizeof(float);   // 180224 B
    cudaFuncSetAttribute(qkv_fused_kernel, cudaFuncAttributeMaxDynamicSharedMemorySize,
                         (int)QKV_SMEM);
    qkv_fused_kernel<<<SEQ * BATCH / 128, 256, QKV_SMEM>>>(x, Wq, bq, Wk, bk, Wv, bv);

    const size_t FLASH_SMEM = 46080;         // bytes: Q 9216 + K 2x9216 + Vt 2x9216
    cudaFuncSetAttribute(flash_kernel, cudaFuncAttributeMaxDynamicSharedMemorySize,
                         (int)FLASH_SMEM);
    flash_kernel<<<SEQ / 64 * BATCH, 256, FLASH_SMEM>>>(out);
}

// round 13
// speedup vs baseline: 1.9702x; 1.1460x over previous
#include <cuda_runtime.h>
#include <cuda_fp16.h>
#include <cstdint>

#define EMBED 768
#define HEAD 64
#define SEQ 4096
#define BATCH 4

// Projections, fp16. g_Qh pre-scaled by 0.125*log2(e) (softmax in log2 domain).
// g_Qh/g_Kh: [B*T, 64] row-major. g_Vth: [B][64 head][4096 seq]
__device__ __half g_Qh[BATCH * SEQ * HEAD];
__device__ __half g_Kh[BATCH * SEQ * HEAD];
__device__ __half g_Vth[BATCH * HEAD * SEQ];

#define QSCALE 0.18033688f   // 0.125 * log2(e)

__device__ __forceinline__ uint32_t h2_to_u32(__half2 h) {
    union { __half2 h; uint32_t u; } cvt;
    cvt.h = h;
    return cvt.u;
}
__device__ __forceinline__ __half2 u32_to_h2(uint32_t u) {
    union { uint32_t u; __half2 h; } cvt;
    cvt.u = u;
    return cvt.h;
}
__device__ __forceinline__ float ex2(float x) {
    float r;
    asm("ex2.approx.ftz.f32 %0, %1;" : "=f"(r) : "f"(x));
    return r;
}

// tf32: D(16x8) += A(16x8) * B(8x8)
__device__ __forceinline__ void mma_tf32(float c[4],
    uint32_t a0, uint32_t a1, uint32_t a2, uint32_t a3,
    uint32_t b0, uint32_t b1)
{
    asm volatile(
        "mma.sync.aligned.m16n8k8.row.col.f32.tf32.tf32.f32 "
        "{%0,%1,%2,%3}, {%4,%5,%6,%7}, {%8,%9}, {%0,%1,%2,%3};"
        : "+f"(c[0]), "+f"(c[1]), "+f"(c[2]), "+f"(c[3])
        : "r"(a0), "r"(a1), "r"(a2), "r"(a3), "r"(b0), "r"(b1));
}

// fp16: D(16x8,f32) += A(16x16,f16) * B(16x8,f16)
__device__ __forceinline__ void mma_f16(float c[4],
    uint32_t a0, uint32_t a1, uint32_t a2, uint32_t a3,
    uint32_t b0, uint32_t b1)
{
    asm volatile(
        "mma.sync.aligned.m16n8k16.row.col.f32.f16.f16.f32 "
        "{%0,%1,%2,%3}, {%4,%5,%6,%7}, {%8,%9}, {%0,%1,%2,%3};"
        : "+f"(c[0]), "+f"(c[1]), "+f"(c[2]), "+f"(c[3])
        : "r"(a0), "r"(a1), "r"(a2), "r"(a3), "r"(b0), "r"(b1));
}

__device__ __forceinline__ uint32_t s2u(const void* p) {
    uint32_t a;
    asm("{ .reg .u64 t; cvta.to.shared.u64 t, %1; cvt.u32.u64 %0, t; }"
        : "=r"(a) : "l"(p));
    return a;
}

#define CPA16(dst, src) \
    asm volatile("cp.async.cg.shared.global [%0], [%1], 16;" :: "r"(dst), "l"(src) : "memory")
#define CPA_COMMIT() asm volatile("cp.async.commit_group;" ::: "memory")
#define CPA_WAIT1()  asm volatile("cp.async.wait_group 1;" ::: "memory")
#define CPA_WAIT0()  asm volatile("cp.async.wait_group 0;" ::: "memory")

// ---------------------------------------------------------------------------
// Fused QKV projection: 2(M) x 4(N) warp decomposition.
// Warp w: mg = w>>2 owns rows 64*mg..64*mg+63 (4 m16 tiles);
//         cg = w&3 owns n8-blocks {2cg, 2cg+1} of EVERY matrix.
// B fragments loaded once per (ks,m,jn) and reused across 4 row-tiles.
// rna rounding via in-register +0x1000 on both operands.
// Grid = 128 blocks (single wave), 256 threads.
// smem (floats): x0[0,8704) x1[8704,17408)
//                W(stage s, matrix m) at 17408 + s*13824 + m*4608  (64x72)
// ---------------------------------------------------------------------------
__global__ __launch_bounds__(256, 1) void qkv_fused_kernel(
    const float* __restrict__ x,
    const float* __restrict__ Wq, const float* __restrict__ bq,
    const float* __restrict__ Wk, const float* __restrict__ bk,
    const float* __restrict__ Wv, const float* __restrict__ bv)
{
    extern __shared__ __align__(16) float qsm[];
    const int XS = 8704, WBASE = 17408, WSTG = 13824, WMAT = 4608;

    const int t    = threadIdx.x;
    const int lane = t & 31;
    const int warp = t >> 5;
    const int mg   = warp >> 2;          // row-group 0/1 (64 rows each)
    const int cg   = warp & 3;           // col-group 0..3 (16 head-cols each)
    const int gid  = lane >> 2;
    const int l3   = lane & 3;
    const int row0 = blockIdx.x * 128;

    const uint32_t su = s2u(qsm);

    // ---- prologue: chunks 0 and 1 ----
#pragma unroll
    for (int st = 0; st < 2; st++) {
        int e0 = st * 64;
        uint32_t xbase = su + (st * XS) * 4;
        uint32_t wbase = su + (WBASE + st * WSTG) * 4;
#pragma unroll
        for (int i = 0; i < 8; i++) {
            int id = t + i * 256;
            int r  = id >> 4;
            int c  = (id & 15) << 2;
            CPA16(xbase + (r * 68 + c) * 4, &x[(size_t)(row0 + r) * EMBED + e0 + c]);
        }
#pragma unroll
        for (int i = 0; i < 12; i++) {
            int id = t + i * 256;
            int m  = id >> 10;
            int rm = id & 1023;
            int r  = rm >> 4;
            int c  = (rm & 15) << 2;
            const float* Wm = (m == 0) ? Wq : (m == 1) ? Wk : Wv;
            CPA16(wbase + (m * WMAT + r * 72 + c) * 4, &Wm[(size_t)(e0 + r) * HEAD + c]);
        }
        CPA_COMMIT();
    }

    float o[4][3][2][4];                 // [mt][m][jn][c]
#pragma unroll
    for (int mt = 0; mt < 4; mt++)
#pragma unroll
        for (int m = 0; m < 3; m++)
#pragma unroll
            for (int j = 0; j < 2; j++)
#pragma unroll
                for (int c = 0; c < 4; c++) o[mt][m][j][c] = 0.f;

    for (int chk = 0; chk < EMBED / 64; chk++) {
        CPA_WAIT1();
        __syncthreads();

        const int st = chk & 1;
        const uint32_t* sx = (const uint32_t*)(qsm + st * XS);
        const uint32_t* sw = (const uint32_t*)(qsm + WBASE + st * WSTG);

#pragma unroll
        for (int ks = 0; ks < 8; ks++) {
            int h = 8 * ks;
            uint32_t af[4][4];
#pragma unroll
            for (int mt = 0; mt < 4; mt++) {
                int row = 64 * mg + 16 * mt + gid;
                af[mt][0] = sx[(row) * 68 + h + l3] + 0x1000u;
                af[mt][1] = sx[(row + 8) * 68 + h + l3] + 0x1000u;
                af[mt][2] = sx[(row) * 68 + h + l3 + 4] + 0x1000u;
                af[mt][3] = sx[(row + 8) * 68 + h + l3 + 4] + 0x1000u;
            }
#pragma unroll
            for (int m = 0; m < 3; m++) {
                const uint32_t* swm = sw + m * WMAT;
#pragma unroll
                for (int j = 0; j < 2; j++) {
                    int n = 2 * cg + j;
                    uint32_t b0 = swm[(h + l3) * 72 + 8 * n + gid] + 0x1000u;
                    uint32_t b1 = swm[(h + l3 + 4) * 72 + 8 * n + gid] + 0x1000u;
#pragma unroll
                    for (int mt = 0; mt < 4; mt++)
                        mma_tf32(o[mt][m][j], af[mt][0], af[mt][1], af[mt][2], af[mt][3], b0, b1);
                }
            }
        }

        __syncthreads();

        if (chk + 2 < EMBED / 64) {
            int e0 = (chk + 2) * 64;
            uint32_t xbase = su + (st * XS) * 4;
            uint32_t wbase = su + (WBASE + st * WSTG) * 4;
#pragma unroll
            for (int i = 0; i < 8; i++) {
                int id = t + i * 256;
                int r  = id >> 4;
                int c  = (id & 15) << 2;
                CPA16(xbase + (r * 68 + c) * 4, &x[(size_t)(row0 + r) * EMBED + e0 + c]);
            }
#pragma unroll
            for (int i = 0; i < 12; i++) {
                int id = t + i * 256;
                int m  = id >> 10;
                int rm = id & 1023;
                int r  = rm >> 4;
                int c  = (rm & 15) << 2;
                const float* Wm = (m == 0) ? Wq : (m == 1) ? Wk : Wv;
                CPA16(wbase + (m * WMAT + r * 72 + c) * 4, &Wm[(size_t)(e0 + r) * HEAD + c]);
            }
        }
        CPA_COMMIT();
    }
    CPA_WAIT0();

    const int bb   = (row0) / SEQ;
    __half* vt = g_Vth + (size_t)bb * HEAD * SEQ;

#pragma unroll
    for (int mt = 0; mt < 4; mt++) {
        const int rowA = row0 + 64 * mg + 16 * mt + gid;
        const int rowB = rowA + 8;
        const int seqA = rowA - bb * SEQ;
#pragma unroll
        for (int j = 0; j < 2; j++) {
            int n  = 2 * cg + j;
            int cb = 8 * n + 2 * l3;
            // Q (pre-scaled by QSCALE for log2-domain softmax)
            {
                float b0 = bq[cb], b1 = bq[cb + 1];
                *(__half2*)&g_Qh[(size_t)rowA * HEAD + cb] =
                    __floats2half2_rn((o[mt][0][j][0] + b0) * QSCALE,
                                      (o[mt][0][j][1] + b1) * QSCALE);
                *(__half2*)&g_Qh[(size_t)rowB * HEAD + cb] =
                    __floats2half2_rn((o[mt][0][j][2] + b0) * QSCALE,
                                      (o[mt][0][j][3] + b1) * QSCALE);
            }
            // K
            {
                float b0 = bk[cb], b1 = bk[cb + 1];
                *(__half2*)&g_Kh[(size_t)rowA * HEAD + cb] =
                    __floats2half2_rn(o[mt][1][j][0] + b0, o[mt][1][j][1] + b1);
                *(__half2*)&g_Kh[(size_t)rowB * HEAD + cb] =
                    __floats2half2_rn(o[mt][1][j][2] + b0, o[mt][1][j][3] + b1);
            }
            // V transposed
            {
                float b0 = bv[cb], b1 = bv[cb + 1];
                vt[(size_t)(cb)     * SEQ + seqA]     = __float2half_rn(o[mt][2][j][0] + b0);
                vt[(size_t)(cb + 1) * SEQ + seqA]     = __float2half_rn(o[mt][2][j][1] + b1);
                vt[(size_t)(cb)     * SEQ + seqA + 8] = __float2half_rn(o[mt][2][j][2] + b0);
                vt[(size_t)(cb + 1) * SEQ + seqA + 8] = __float2half_rn(o[mt][2][j][3] + b1);
            }
        }
    }
}

// ---------------------------------------------------------------------------
// Flash attention: causal, fp16 m16n8k16, split-kn across 2 warp-groups,
// register-resident Q frags + P, LPT-balanced tiles.
// 3-stage K/V cp.async ring, prefetch distance 2, ONE __syncthreads per iter
// (prefetch target slot (kt+2)%3 == (kt-1)%3 was consumed before the top-of-
// iter barrier). Softmax in log2 domain (Q pre-scaled; ex2.approx).
// smem bytes: Q[0,9216) K stage s at 9216+9216s (s<3), V at 36864+9216s.
// Total 64512 B -> 2 blocks/SM.
// ---------------------------------------------------------------------------
__global__ __launch_bounds__(256, 2) void flash_kernel(float* __restrict__ out)
{
    extern __shared__ __align__(16) unsigned char smraw[];
    __half* sh = (__half*)smraw;
    __half* sQ = sh;                     // 64 x 72 halves

    const int bid = blockIdx.x;
    const int rr  = (bid < 148) ? bid : 403 - bid;
    const int qt  = 63 - (rr >> 2);
    const int b   = rr & 3;

    const int t    = threadIdx.x;
    const int lane = t & 31;
    const int warp = t >> 5;
    const int g    = warp >> 2;          // column-group 0/1
    const int w16  = (warp & 3) << 4;
    const int gid  = lane >> 2;
    const int l3   = lane & 3;
    const int r0   = w16 + gid;
    const int l2   = 2 * l3;

    const __half* __restrict__ Qg = g_Qh + (size_t)b * SEQ * HEAD;
    const __half* __restrict__ Kg = g_Kh + (size_t)b * SEQ * HEAD;
    const __half* __restrict__ Vg = g_Vth + (size_t)b * HEAD * SEQ;

    const uint32_t su = s2u(sh);

    // g0: Q + K0 + V0
#pragma unroll
    for (int i = 0; i < 2; i++) {
        int id = t + i * 256;
        int r  = id >> 3;
        int ch = id & 7;
        CPA16(su + r * 144 + 16 * ch, Qg + (size_t)(qt * 64 + r) * HEAD + 8 * ch);
        CPA16(su + 9216 + r * 144 + 16 * ch, Kg + (size_t)r * HEAD + 8 * ch);
        CPA16(su + 36864 + r * 144 + 16 * ch, Vg + (size_t)r * SEQ + 8 * ch);
    }
    CPA_COMMIT();
    // g1: K1 + V1
#pragma unroll
    for (int i = 0; i < 2; i++) {
        int id = t + i * 256;
        int r  = id >> 3;
        int ch = id & 7;
        CPA16(su + 9216 + 9216 + r * 144 + 16 * ch,
              Kg + (size_t)(64 + r) * HEAD + 8 * ch);
        CPA16(su + 36864 + 9216 + r * 144 + 16 * ch,
              Vg + (size_t)r * SEQ + 64 + 8 * ch);
    }
    CPA_COMMIT();

    CPA_WAIT1();            // g0 (Q + stage0) landed
    __syncthreads();
    uint32_t qf[4][4];
#pragma unroll
    for (int ks = 0; ks < 4; ks++) {
        int k0 = 16 * ks;
        qf[ks][0] = *(const uint32_t*)&sQ[(r0) * 72 + k0 + l2];
        qf[ks][1] = *(const uint32_t*)&sQ[(r0 + 8) * 72 + k0 + l2];
        qf[ks][2] = *(const uint32_t*)&sQ[(r0) * 72 + k0 + l2 + 8];
        qf[ks][3] = *(const uint32_t*)&sQ[(r0 + 8) * 72 + k0 + l2 + 8];
    }

    float m0 = -1e30f, m1 = -1e30f, l0 = 0.f, l1 = 0.f;
    float o[8][4];
#pragma unroll
    for (int n = 0; n < 8; n++)
#pragma unroll
        for (int c = 0; c < 4; c++) o[n][c] = 0.f;

    int st = 0;
    for (int kt = 0; kt <= qt; kt++) {
        CPA_WAIT1();
        __syncthreads();

        const __half* sKc = sh + 4608 + st * 4608;
        const __half* sVc = sh + 18432 + st * 4608;

        float s[4][4];
#pragma unroll
        for (int n = 0; n < 4; n++)
#pragma unroll
            for (int c = 0; c < 4; c++) s[n][c] = 0.f;

#pragma unroll
        for (int ks = 0; ks < 4; ks++) {
            int k0 = 16 * ks;
#pragma unroll
            for (int n = 0; n < 4; n++) {
                int kr = 32 * g + 8 * n + gid;
                uint32_t b0 = *(const uint32_t*)&sKc[kr * 72 + k0 + l2];
                uint32_t b1 = *(const uint32_t*)&sKc[kr * 72 + k0 + l2 + 8];
                mma_f16(s[n], qf[ks][0], qf[ks][1], qf[ks][2], qf[ks][3], b0, b1);
            }
        }

        // Causal mask only (S already scaled: Q carries 0.125*log2e)
        if (kt == qt) {
#pragma unroll
            for (int n = 0; n < 4; n++) {
                int c0 = 32 * g + 8 * n + l2;
                if (c0     > r0    ) s[n][0] = -1e30f;
                if (c0 + 1 > r0    ) s[n][1] = -1e30f;
                if (c0     > r0 + 8) s[n][2] = -1e30f;
                if (c0 + 1 > r0 + 8) s[n][3] = -1e30f;
            }
        }

        float mx0 = fmaxf(fmaxf(s[0][0], s[0][1]), fmaxf(s[1][0], s[1][1]));
        mx0 = fmaxf(mx0, fmaxf(fmaxf(s[2][0], s[2][1]), fmaxf(s[3][0], s[3][1])));
        float mx1 = fmaxf(fmaxf(s[0][2], s[0][3]), fmaxf(s[1][2], s[1][3]));
        mx1 = fmaxf(mx1, fmaxf(fmaxf(s[2][2], s[2][3]), fmaxf(s[3][2], s[3][3])));

        __half2 hmx = __floats2half2_rn(mx0, mx1);
        hmx = __hmax2(hmx, u32_to_h2(__shfl_xor_sync(0xffffffffu, h2_to_u32(hmx), 1)));
        hmx = __hmax2(hmx, u32_to_h2(__shfl_xor_sync(0xffffffffu, h2_to_u32(hmx), 2)));
        float2 fmx = __half22float2(hmx);

        float mn0 = fmaxf(m0, fmx.x);
        float mn1 = fmaxf(m1, fmx.y);
        float alpha0 = ex2(m0 - mn0);
        float alpha1 = ex2(m1 - mn1);
        m0 = mn0; m1 = mn1;

        float rs0 = 0.f, rs1 = 0.f;
#pragma unroll
        for (int n = 0; n < 4; n++) {
            s[n][0] = ex2(s[n][0] - mn0);
            s[n][1] = ex2(s[n][1] - mn0);
            s[n][2] = ex2(s[n][2] - mn1);
            s[n][3] = ex2(s[n][3] - mn1);
            rs0 += s[n][0] + s[n][1];
            rs1 += s[n][2] + s[n][3];
        }
        l0 = l0 * alpha0 + rs0;
        l1 = l1 * alpha1 + rs1;

#pragma unroll
        for (int n = 0; n < 8; n++) {
            o[n][0] *= alpha0; o[n][1] *= alpha0;
            o[n][2] *= alpha1; o[n][3] *= alpha1;
        }

        uint32_t p[8];
#pragma unroll
        for (int n = 0; n < 4; n++) {
            p[2 * n]     = h2_to_u32(__floats2half2_rn(s[n][0], s[n][1]));
            p[2 * n + 1] = h2_to_u32(__floats2half2_rn(s[n][2], s[n][3]));
        }

#pragma unroll
        for (int ks = 0; ks < 2; ks++) {
            uint32_t a0 = p[4 * ks + 0];
            uint32_t a1 = p[4 * ks + 1];
            uint32_t a2 = p[4 * ks + 2];
            uint32_t a3 = p[4 * ks + 3];
            int kb = 32 * g + 16 * ks + l2;
#pragma unroll
            for (int n = 0; n < 8; n++) {
                int vr = 8 * n + gid;
                uint32_t b0 = *(const uint32_t*)&sVc[vr * 72 + kb];
                uint32_t b1 = *(const uint32_t*)&sVc[vr * 72 + kb + 8];
                mma_f16(o[n], a0, a1, a2, a3, b0, b1);
            }
        }

        // Prefetch stage kt+2 into slot (kt+2)%3 (freed as of this iter's barrier)
        if (kt + 2 <= qt) {
            int ps = st + 2;
            if (ps >= 3) ps -= 3;
#pragma unroll
            for (int i = 0; i < 2; i++) {
                int id = t + i * 256;
                int r  = id >> 3;
                int ch = id & 7;
                CPA16(su + 9216 + ps * 9216 + r * 144 + 16 * ch,
                      Kg + (size_t)((kt + 2) * 64 + r) * HEAD + 8 * ch);
                CPA16(su + 36864 + ps * 9216 + r * 144 + 16 * ch,
                      Vg + (size_t)r * SEQ + (kt + 2) * 64 + 8 * ch);
            }
        }
        CPA_COMMIT();
        if (++st == 3) st = 0;
    }

    CPA_WAIT0();
    __syncthreads();

    l0 += __shfl_xor_sync(0xffffffffu, l0, 1);
    l0 += __shfl_xor_sync(0xffffffffu, l0, 2);
    l1 += __shfl_xor_sync(0xffffffffu, l1, 1);
    l1 += __shfl_xor_sync(0xffffffffu, l1, 2);

    float* sML = (float*)smraw;
    if (l3 == 0) {
        sML[((g * 64 + r0)     << 1) + 0] = m0;
        sML[((g * 64 + r0)     << 1) + 1] = l0;
        sML[((g * 64 + r0 + 8) << 1) + 0] = m1;
        sML[((g * 64 + r0 + 8) << 1) + 1] = l1;
    }
    __syncthreads();
    const int og = 1 - g;
    float mo0 = sML[((og * 64 + r0)     << 1) + 0];
    float lo0 = sML[((og * 64 + r0)     << 1) + 1];
    float mo1 = sML[((og * 64 + r0 + 8) << 1) + 0];
    float lo1 = sML[((og * 64 + r0 + 8) << 1) + 1];

    float M0 = fmaxf(m0, mo0), M1 = fmaxf(m1, mo1);
    float sc0 = ex2(m0 - M0), sc1 = ex2(m1 - M1);
    float L0 = l0 * sc0 + lo0 * ex2(mo0 - M0);
    float L1 = l1 * sc1 + lo1 * ex2(mo1 - M1);

#pragma unroll
    for (int n = 0; n < 8; n++) {
        o[n][0] *= sc0; o[n][1] *= sc0;
        o[n][2] *= sc1; o[n][3] *= sc1;
    }

    float* sOB = (float*)(smraw + 9216);
    if (g == 1) {
#pragma unroll
        for (int n = 0; n < 8; n++) {
            int cb = 8 * n + l2;
            sOB[(r0) * 68 + cb + 0]     = o[n][0];
            sOB[(r0) * 68 + cb + 1]     = o[n][1];
            sOB[(r0 + 8) * 68 + cb + 0] = o[n][2];
            sOB[(r0 + 8) * 68 + cb + 1] = o[n][3];
        }
    }
    __syncthreads();
    if (g == 0) {
        float inv0 = 1.f / L0;
        float inv1 = 1.f / L1;
        size_t orow0 = (size_t)b * SEQ + qt * 64 + r0;
#pragma unroll
        for (int n = 0; n < 8; n++) {
            int cb = 8 * n + l2;
            float2 v0, v1;
            v0.x = (o[n][0] + sOB[(r0) * 68 + cb + 0])     * inv0;
            v0.y = (o[n][1] + sOB[(r0) * 68 + cb + 1])     * inv0;
            v1.x = (o[n][2] + sOB[(r0 + 8) * 68 + cb + 0]) * inv1;
            v1.y = (o[n][3] + sOB[(r0 + 8) * 68 + cb + 1]) * inv1;
            *(float2*)&out[orow0 * HEAD + cb]       = v0;
            *(float2*)&out[(orow0 + 8) * HEAD + cb] = v1;
        }
    }
}

extern "C" void kernel_launch(void* const* d_in, const int* in_sizes, int n_in,
                              void* d_out, int out_size)
{
    const float* x  = (const float*)d_in[0];
    const float* Wq = (const float*)d_in[1];
    const float* bq = (const float*)d_in[2];
    const float* Wk = (const float*)d_in[3];
    const float* bk = (const float*)d_in[4];
    const float* Wv = (const float*)d_in[5];
    const float* bv = (const float*)d_in[6];
    float* out = (float*)d_out;

    const size_t QKV_SMEM = (size_t)45056 * sizeof(float);   // 180224 B
    cudaFuncSetAttribute(qkv_fused_kernel, cudaFuncAttributeMaxDynamicSharedMemorySize,
                         (int)QKV_SMEM);
    qkv_fused_kernel<<<SEQ * BATCH / 128, 256, QKV_SMEM>>>(x, Wq, bq, Wk, bk, Wv, bv);

    const size_t FLASH_SMEM = 64512;     // bytes: Q 9216 + K 3x9216 + Vt 3x9216
    cudaFuncSetAttribute(flash_kernel, cudaFuncAttributeMaxDynamicSharedMemorySize,
                         (int)FLASH_SMEM);
    flash_kernel<<<SEQ / 64 * BATCH, 256, FLASH_SMEM>>>(out);
}